// round 4
// baseline (speedup 1.0000x reference)
#include <cuda_runtime.h>

#define B_ 8
#define C_ 256
#define H_ 128
#define W_ 128
#define NEL (B_*C_*H_*W_)

// Scratch (no allocation allowed -> __device__ globals)
__device__ float g_tmp[NEL];
__device__ float g_q[NEL];   // layout [b][h][w][c]  (pre-transposed for attention)
__device__ float g_k[NEL];   // layout [b][h][w][c]
__device__ float g_v[NEL];   // layout [b][h][c][w]

// ---------------------------------------------------------------------------
// Depthwise 3x3 (SAME, cross-correlation) + bias.  Memory-bound, simple.
// grid (H, C, B), block 128 (one thread per w)
// ---------------------------------------------------------------------------
__global__ __launch_bounds__(128) void dw_kernel(
    const float* __restrict__ x, const float* __restrict__ wgt,
    const float* __restrict__ bias, float* __restrict__ out)
{
    const int h = blockIdx.x, c = blockIdx.y, b = blockIdx.z;
    const int w = threadIdx.x;
    const float* wc = wgt + c * 9;
    const float* plane = x + (b * C_ + c) * (H_ * W_);
    float acc = __ldg(&bias[c]);
    #pragma unroll
    for (int i = 0; i < 3; i++) {
        int hh = h + i - 1;
        if (hh < 0 || hh >= H_) continue;
        const float* row = plane + hh * W_;
        float xl = (w > 0)      ? __ldg(&row[w-1]) : 0.f;
        float xc =                __ldg(&row[w]);
        float xr = (w < W_-1)   ? __ldg(&row[w+1]) : 0.f;
        acc += __ldg(&wc[i*3+0]) * xl + __ldg(&wc[i*3+1]) * xc + __ldg(&wc[i*3+2]) * xr;
    }
    out[(b * C_ + c) * (H_*W_) + h * W_ + w] = acc;
}

// ---------------------------------------------------------------------------
// Pointwise 1x1: per (b,h): out[o,w] = bias[o] + sum_c W[o,c]*t[b,c,h,w]
// CTA tile 128(o) x 128(w), 256 threads = (tx 32 over w, ty 8 over o),
// thread tile 16(o) x 4(w).  A stored transposed At[c][o] in smem so the
// A-fragment read is a warp-broadcast LDS.128; B-fragment read conflict-free.
// TRANS=1 writes [b][h][w][c] (for q,k); TRANS=0 writes [b][h][c][w] (for v).
// grid (2, H, B)
// ---------------------------------------------------------------------------
#define PW_AP 132
#define PW_BP 132

template<int TRANS>
__global__ __launch_bounds__(256, 2) void pw_kernel(
    const float* __restrict__ t, const float* __restrict__ Wm,
    const float* __restrict__ bias, float* __restrict__ out)
{
    __shared__ float At[16 * PW_AP];
    __shared__ float Bs[16 * PW_BP];
    const int o0 = blockIdx.x * 128;
    const int h = blockIdx.y, b = blockIdx.z;
    const int tid = threadIdx.x;
    const int tx = tid & 31, ty = tid >> 5;

    float acc[16][4];
    #pragma unroll
    for (int i = 0; i < 16; i++) { acc[i][0]=0.f; acc[i][1]=0.f; acc[i][2]=0.f; acc[i][3]=0.f; }

    const int o_l = tid >> 1, cg = (tid & 1) * 8;   // A loader mapping
    const int c_l = tid >> 4, wg = (tid & 15) * 8;  // B loader mapping
    const float* tb = t + b * (C_ * H_ * W_) + h * W_;

    for (int kk = 0; kk < C_; kk += 16) {
        __syncthreads();
        // A tile: W[o0+o_l][kk+cg .. +7] -> At[c][o] (transposed store)
        {
            const float* wr = Wm + (o0 + o_l) * C_ + kk + cg;
            float4 wa = *(const float4*)wr;
            float4 wb = *(const float4*)(wr + 4);
            At[(cg+0)*PW_AP + o_l] = wa.x;
            At[(cg+1)*PW_AP + o_l] = wa.y;
            At[(cg+2)*PW_AP + o_l] = wa.z;
            At[(cg+3)*PW_AP + o_l] = wa.w;
            At[(cg+4)*PW_AP + o_l] = wb.x;
            At[(cg+5)*PW_AP + o_l] = wb.y;
            At[(cg+6)*PW_AP + o_l] = wb.z;
            At[(cg+7)*PW_AP + o_l] = wb.w;
        }
        // B tile: t[b][kk+c_l][h][wg..+7]
        {
            const float* br = tb + (kk + c_l) * (H_ * W_) + wg;
            *(float4*)&Bs[c_l*PW_BP + wg]     = *(const float4*)br;
            *(float4*)&Bs[c_l*PW_BP + wg + 4] = *(const float4*)(br + 4);
        }
        __syncthreads();
        #pragma unroll
        for (int c = 0; c < 16; c++) {
            float4 a0 = *(const float4*)&At[c*PW_AP + ty*16];
            float4 a1 = *(const float4*)&At[c*PW_AP + ty*16 + 4];
            float4 a2 = *(const float4*)&At[c*PW_AP + ty*16 + 8];
            float4 a3 = *(const float4*)&At[c*PW_AP + ty*16 + 12];
            float4 bf = *(const float4*)&Bs[c*PW_BP + tx*4];
            float av[16] = {a0.x,a0.y,a0.z,a0.w, a1.x,a1.y,a1.z,a1.w,
                            a2.x,a2.y,a2.z,a2.w, a3.x,a3.y,a3.z,a3.w};
            #pragma unroll
            for (int i = 0; i < 16; i++) {
                acc[i][0] += av[i]*bf.x;
                acc[i][1] += av[i]*bf.y;
                acc[i][2] += av[i]*bf.z;
                acc[i][3] += av[i]*bf.w;
            }
        }
    }

    float bo[16];
    #pragma unroll
    for (int i = 0; i < 16; i++) bo[i] = __ldg(&bias[o0 + ty*16 + i]);

    if (TRANS) {
        float* ob = out + (b * H_ + h) * (W_ * C_);
        #pragma unroll
        for (int j = 0; j < 4; j++) {
            float* op = ob + (tx*4 + j) * C_ + o0 + ty*16;
            #pragma unroll
            for (int i4 = 0; i4 < 4; i4++) {
                float4 v4;
                v4.x = acc[i4*4+0][j] + bo[i4*4+0];
                v4.y = acc[i4*4+1][j] + bo[i4*4+1];
                v4.z = acc[i4*4+2][j] + bo[i4*4+2];
                v4.w = acc[i4*4+3][j] + bo[i4*4+3];
                *(float4*)(op + i4*4) = v4;
            }
        }
    } else {
        float* ob = out + ((b * H_ + h) * C_ + o0 + ty*16) * W_ + tx*4;
        #pragma unroll
        for (int i = 0; i < 16; i++) {
            float4 v4 = make_float4(acc[i][0]+bo[i], acc[i][1]+bo[i],
                                    acc[i][2]+bo[i], acc[i][3]+bo[i]);
            *(float4*)(ob + i * W_) = v4;
        }
    }
}

// ---------------------------------------------------------------------------
// Attention: one CTA per (b, h, 64-row q tile).  Full score rows (64x256) in
// smem -> exact softmax, no online rescale.  K/V streamed as two 128-chunks
// through one shared buffer.  grid (4, H, B), 256 threads (tx 32, ty 8).
// Thread tile: 8 rows (r=ty*8+i) x 4 cols.
// ---------------------------------------------------------------------------
#define AQP 68
#define AKP 132
#define ASP 260
#define ATT_SMEM ((128*AQP + 128*AKP + 64*ASP + 64) * 4)

__global__ __launch_bounds__(256, 1) void attn_kernel(
    const float* __restrict__ q, const float* __restrict__ k,
    const float* __restrict__ v, float* __restrict__ out)
{
    extern __shared__ float sm[];
    float* Qt   = sm;                 // [w 128][r 64]   (pitch AQP)
    float* KV   = sm + 128*AQP;       // [128][128]      (pitch AKP), K then V
    float* S    = KV + 128*AKP;       // [r 64][d 256]   (pitch ASP)
    float* linv = S + 64*ASP;         // [64]

    const int q0 = blockIdx.x * 64;
    const int h = blockIdx.y, b = blockIdx.z;
    const int tid = threadIdx.x;
    const int tx = tid & 31, ty = tid >> 5;
    const float scale = 0.17677669529663687f;  // 1/sqrt(32)

    const int bh = b * H_ + h;
    const float* qb = q + bh * (W_ * C_);   // [w][c]
    const float* kb = k + bh * (W_ * C_);   // [w][c]
    const float* vb = v + bh * (C_ * W_);   // [c][w]

    // Load Q tile transposed-from-gmem (gmem already [w][c]): Qt[w][r]
    for (int idx = tid; idx < 128*16; idx += 256) {
        int w = idx >> 4, c4 = idx & 15;
        *(float4*)&Qt[w*AQP + c4*4] = *(const float4*)(qb + w*C_ + q0 + c4*4);
    }

    // S = scale * Q K^T, two 128-wide d-chunks
    for (int dt = 0; dt < 2; dt++) {
        __syncthreads();
        for (int idx = tid; idx < 128*32; idx += 256) {
            int w = idx >> 5, d4 = idx & 31;
            *(float4*)&KV[w*AKP + d4*4] = *(const float4*)(kb + w*C_ + dt*128 + d4*4);
        }
        __syncthreads();
        float sacc[8][4];
        #pragma unroll
        for (int i = 0; i < 8; i++) { sacc[i][0]=0.f; sacc[i][1]=0.f; sacc[i][2]=0.f; sacc[i][3]=0.f; }
        #pragma unroll 4
        for (int w = 0; w < 128; w++) {
            float4 qa = *(const float4*)&Qt[w*AQP + ty*8];       // warp-broadcast
            float4 qc = *(const float4*)&Qt[w*AQP + ty*8 + 4];
            float4 kf = *(const float4*)&KV[w*AKP + tx*4];       // conflict-free
            float qr[8] = {qa.x,qa.y,qa.z,qa.w, qc.x,qc.y,qc.z,qc.w};
            #pragma unroll
            for (int i = 0; i < 8; i++) {
                sacc[i][0] += qr[i]*kf.x;
                sacc[i][1] += qr[i]*kf.y;
                sacc[i][2] += qr[i]*kf.z;
                sacc[i][3] += qr[i]*kf.w;
            }
        }
        #pragma unroll
        for (int i = 0; i < 8; i++) {
            float4 v4 = make_float4(sacc[i][0]*scale, sacc[i][1]*scale,
                                    sacc[i][2]*scale, sacc[i][3]*scale);
            *(float4*)&S[(ty*8+i)*ASP + dt*128 + tx*4] = v4;
        }
    }
    __syncthreads();

    // Softmax over full 256-wide rows: 4 threads per row
    {
        int r = tid >> 2, qq = tid & 3;
        float* srow = S + r*ASP + qq*64;
        float m = -1e30f;
        for (int j = 0; j < 64; j++) m = fmaxf(m, srow[j]);
        m = fmaxf(m, __shfl_xor_sync(0xffffffffu, m, 1));
        m = fmaxf(m, __shfl_xor_sync(0xffffffffu, m, 2));
        float l = 0.f;
        for (int j = 0; j < 64; j++) { float e = __expf(srow[j] - m); srow[j] = e; l += e; }
        l += __shfl_xor_sync(0xffffffffu, l, 1);
        l += __shfl_xor_sync(0xffffffffu, l, 2);
        if (qq == 0) linv[r] = 1.f / l;
    }

    // O = P V  (normalize by 1/l at the end)
    float oacc[8][4];
    #pragma unroll
    for (int i = 0; i < 8; i++) { oacc[i][0]=0.f; oacc[i][1]=0.f; oacc[i][2]=0.f; oacc[i][3]=0.f; }

    for (int dt = 0; dt < 2; dt++) {
        __syncthreads();
        for (int idx = tid; idx < 128*32; idx += 256) {
            int d = idx >> 5, w4 = idx & 31;
            *(float4*)&KV[d*AKP + w4*4] = *(const float4*)(vb + (dt*128 + d)*W_ + w4*4);
        }
        __syncthreads();
        for (int d = 0; d < 128; d += 4) {
            float4 pf[8];
            #pragma unroll
            for (int i = 0; i < 8; i++)
                pf[i] = *(const float4*)&S[(ty*8+i)*ASP + dt*128 + d];   // warp-broadcast
            #pragma unroll
            for (int dd = 0; dd < 4; dd++) {
                float4 vf = *(const float4*)&KV[(d+dd)*AKP + tx*4];      // conflict-free
                #pragma unroll
                for (int i = 0; i < 8; i++) {
                    float p = (dd==0)?pf[i].x:((dd==1)?pf[i].y:((dd==2)?pf[i].z:pf[i].w));
                    oacc[i][0] += p*vf.x;
                    oacc[i][1] += p*vf.y;
                    oacc[i][2] += p*vf.z;
                    oacc[i][3] += p*vf.w;
                }
            }
        }
    }

    #pragma unroll
    for (int i = 0; i < 8; i++) {
        float inv = linv[ty*8 + i];
        int cc = q0 + ty*8 + i;
        float4 v4 = make_float4(oacc[i][0]*inv, oacc[i][1]*inv,
                                oacc[i][2]*inv, oacc[i][3]*inv);
        *(float4*)(out + ((b*C_ + cc)*H_ + h)*W_ + tx*4) = v4;
    }
}

// ---------------------------------------------------------------------------
extern "C" void kernel_launch(void* const* d_in, const int* in_sizes, int n_in,
                              void* d_out, int out_size)
{
    (void)in_sizes; (void)n_in; (void)out_size;
    const float* hidden = (const float*)d_in[0];
    const float* ctx    = (const float*)d_in[1];
    const float* qdw = (const float*)d_in[2];
    const float* qdb = (const float*)d_in[3];
    const float* qpw = (const float*)d_in[4];
    const float* qpb = (const float*)d_in[5];
    const float* kdw = (const float*)d_in[6];
    const float* kdb = (const float*)d_in[7];
    const float* kpw = (const float*)d_in[8];
    const float* kpb = (const float*)d_in[9];
    const float* vdw = (const float*)d_in[10];
    const float* vdb = (const float*)d_in[11];
    const float* vpw = (const float*)d_in[12];
    const float* vpb = (const float*)d_in[13];
    float* out = (float*)d_out;

    float *tmp, *qp, *kp, *vp;
    cudaGetSymbolAddress((void**)&tmp, g_tmp);
    cudaGetSymbolAddress((void**)&qp,  g_q);
    cudaGetSymbolAddress((void**)&kp,  g_k);
    cudaGetSymbolAddress((void**)&vp,  g_v);

    cudaFuncSetAttribute(attn_kernel, cudaFuncAttributeMaxDynamicSharedMemorySize, ATT_SMEM);

    dim3 dwg(H_, C_, B_);
    dim3 pwg(2, H_, B_);
    dim3 atg(4, H_, B_);

    dw_kernel<<<dwg, 128>>>(hidden, qdw, qdb, tmp);
    pw_kernel<1><<<pwg, 256>>>(tmp, qpw, qpb, qp);   // q -> [b][h][w][c]
    dw_kernel<<<dwg, 128>>>(ctx, kdw, kdb, tmp);
    pw_kernel<1><<<pwg, 256>>>(tmp, kpw, kpb, kp);   // k -> [b][h][w][c]
    dw_kernel<<<dwg, 128>>>(ctx, vdw, vdb, tmp);
    pw_kernel<0><<<pwg, 256>>>(tmp, vpw, vpb, vp);   // v -> [b][h][c][w]
    attn_kernel<<<atg, 256, ATT_SMEM>>>(qp, kp, vp, out);
}

// round 5
// speedup vs baseline: 1.8096x; 1.8096x over previous
#include <cuda_runtime.h>

#define B_ 8
#define C_ 256
#define H_ 128
#define W_ 128
#define NEL (B_*C_*H_*W_)

// Scratch (no allocation allowed -> __device__ globals)
__device__ float g_tmp[NEL];
__device__ float g_q[NEL];   // [b][h][w][c]
__device__ float g_k[NEL];   // [b][h][w][c]
__device__ float g_v[NEL];   // [b][h][c][w]

typedef unsigned long long ull;

// ---- packed fp32x2 helpers (FFMA2: ptxas never emits these from C++) ----
__device__ __forceinline__ void ffma2(ull& d, ull a, ull b) {
    asm("fma.rn.f32x2 %0, %1, %2, %3;" : "=l"(d) : "l"(a), "l"(b), "l"(d));
}
__device__ __forceinline__ ull mul2(ull a, ull b) {
    ull r; asm("mul.rn.f32x2 %0, %1, %2;" : "=l"(r) : "l"(a), "l"(b)); return r;
}
__device__ __forceinline__ ull pack2(float x) {
    ull r; asm("mov.b64 %0, {%1, %1};" : "=l"(r) : "f"(x)); return r;
}
__device__ __forceinline__ float2 unpack2(ull a) {
    float2 f; asm("mov.b64 {%0, %1}, %2;" : "=f"(f.x), "=f"(f.y) : "l"(a)); return f;
}

// ---------------------------------------------------------------------------
// Depthwise 3x3 (SAME) + bias.  Memory-bound.
// grid (H, C, B), block 128
// ---------------------------------------------------------------------------
__global__ __launch_bounds__(128) void dw_kernel(
    const float* __restrict__ x, const float* __restrict__ wgt,
    const float* __restrict__ bias, float* __restrict__ out)
{
    const int h = blockIdx.x, c = blockIdx.y, b = blockIdx.z;
    const int w = threadIdx.x;
    const float* wc = wgt + c * 9;
    const float* plane = x + (b * C_ + c) * (H_ * W_);
    float acc = __ldg(&bias[c]);
    #pragma unroll
    for (int i = 0; i < 3; i++) {
        int hh = h + i - 1;
        if (hh < 0 || hh >= H_) continue;
        const float* row = plane + hh * W_;
        float xl = (w > 0)      ? __ldg(&row[w-1]) : 0.f;
        float xc =                __ldg(&row[w]);
        float xr = (w < W_-1)   ? __ldg(&row[w+1]) : 0.f;
        acc += __ldg(&wc[i*3+0]) * xl + __ldg(&wc[i*3+1]) * xc + __ldg(&wc[i*3+2]) * xr;
    }
    out[(b * C_ + c) * (H_*W_) + h * W_ + w] = acc;
}

// ---------------------------------------------------------------------------
// Pointwise 1x1 GEMM with packed FFMA2.  CTA 128(o) x 128(w), 256 threads,
// thread tile 16(o) x 4(w); accumulators as 8 o-pairs x 4 w (ull).
// A stored transposed At[c][o] (o contiguous -> pair loads), B fragment
// scalars packed to both lanes (ALU pipe, dual-issues with FFMA2).
// ---------------------------------------------------------------------------
#define PW_AP 132
#define PW_BP 132

template<int TRANS>
__global__ __launch_bounds__(256, 2) void pw_kernel(
    const float* __restrict__ t, const float* __restrict__ Wm,
    const float* __restrict__ bias, float* __restrict__ out)
{
    __shared__ float At[16 * PW_AP];
    __shared__ float Bs[16 * PW_BP];
    const int o0 = blockIdx.x * 128;
    const int h = blockIdx.y, b = blockIdx.z;
    const int tid = threadIdx.x;
    const int tx = tid & 31, ty = tid >> 5;

    ull acc2[8][4];
    #pragma unroll
    for (int p = 0; p < 8; p++) { acc2[p][0]=0ULL; acc2[p][1]=0ULL; acc2[p][2]=0ULL; acc2[p][3]=0ULL; }

    const int o_l = tid >> 1, cg = (tid & 1) * 8;   // A loader mapping
    const int c_l = tid >> 4, wg = (tid & 15) * 8;  // B loader mapping
    const float* tb = t + b * (C_ * H_ * W_) + h * W_;

    for (int kk = 0; kk < C_; kk += 16) {
        __syncthreads();
        {   // A tile: W[o0+o_l][kk+cg..+7] -> At[c][o]
            const float* wr = Wm + (o0 + o_l) * C_ + kk + cg;
            float4 wa = *(const float4*)wr;
            float4 wb = *(const float4*)(wr + 4);
            At[(cg+0)*PW_AP + o_l] = wa.x;
            At[(cg+1)*PW_AP + o_l] = wa.y;
            At[(cg+2)*PW_AP + o_l] = wa.z;
            At[(cg+3)*PW_AP + o_l] = wa.w;
            At[(cg+4)*PW_AP + o_l] = wb.x;
            At[(cg+5)*PW_AP + o_l] = wb.y;
            At[(cg+6)*PW_AP + o_l] = wb.z;
            At[(cg+7)*PW_AP + o_l] = wb.w;
        }
        {   // B tile: t[b][kk+c_l][h][wg..+7]
            const float* br = tb + (kk + c_l) * (H_ * W_) + wg;
            *(float4*)&Bs[c_l*PW_BP + wg]     = *(const float4*)br;
            *(float4*)&Bs[c_l*PW_BP + wg + 4] = *(const float4*)(br + 4);
        }
        __syncthreads();
        #pragma unroll
        for (int c = 0; c < 16; c++) {
            const ull* ar = (const ull*)&At[c*PW_AP + ty*16];   // 8 o-pairs (broadcast)
            float4 bf = *(const float4*)&Bs[c*PW_BP + tx*4];    // conflict-free
            ull b0 = pack2(bf.x), b1 = pack2(bf.y), b2 = pack2(bf.z), b3 = pack2(bf.w);
            #pragma unroll
            for (int p = 0; p < 8; p++) {
                ull a = ar[p];
                ffma2(acc2[p][0], a, b0);
                ffma2(acc2[p][1], a, b1);
                ffma2(acc2[p][2], a, b2);
                ffma2(acc2[p][3], a, b3);
            }
        }
    }

    float bo[16];
    #pragma unroll
    for (int i = 0; i < 16; i++) bo[i] = __ldg(&bias[o0 + ty*16 + i]);

    if (TRANS) {
        float* ob = out + (b * H_ + h) * (W_ * C_);
        #pragma unroll
        for (int j = 0; j < 4; j++) {
            float* op = ob + (tx*4 + j) * C_ + o0 + ty*16;
            #pragma unroll
            for (int p4 = 0; p4 < 4; p4++) {
                float2 e0 = unpack2(acc2[p4*2][j]);
                float2 e1 = unpack2(acc2[p4*2+1][j]);
                float4 v4 = make_float4(e0.x + bo[p4*4+0], e0.y + bo[p4*4+1],
                                        e1.x + bo[p4*4+2], e1.y + bo[p4*4+3]);
                *(float4*)(op + p4*4) = v4;
            }
        }
    } else {
        float* ob = out + ((b * H_ + h) * C_ + o0 + ty*16) * W_ + tx*4;
        #pragma unroll
        for (int p = 0; p < 8; p++) {
            float2 f0 = unpack2(acc2[p][0]);
            float2 f1 = unpack2(acc2[p][1]);
            float2 f2 = unpack2(acc2[p][2]);
            float2 f3 = unpack2(acc2[p][3]);
            float blo = bo[2*p], bhi = bo[2*p+1];
            *(float4*)(ob + (2*p)*W_)   = make_float4(f0.x+blo, f1.x+blo, f2.x+blo, f3.x+blo);
            *(float4*)(ob + (2*p+1)*W_) = make_float4(f0.y+bhi, f1.y+bhi, f2.y+bhi, f3.y+bhi);
        }
    }
}

// ---------------------------------------------------------------------------
// Attention: one CTA per (b, h, 64-row q tile).  2-chunk ONLINE softmax so
// smem drops to ~101KB -> 2 CTAs/SM (16 warps).  K/V streamed through a
// 64x128 buffer in halves.  256 threads (tx 32, ty 8).  FFMA2 inner loops.
// ---------------------------------------------------------------------------
#define AQP 68
#define AKP 132
#define ASP 132
#define ATT_SMEM ((128*AQP + 64*AKP + 64*ASP + 192) * 4)

__global__ __launch_bounds__(256, 2) void attn_kernel(
    const float* __restrict__ q, const float* __restrict__ k,
    const float* __restrict__ v, float* __restrict__ out)
{
    extern __shared__ float sm[];
    float* Qt     = sm;                 // [w 128][r 64]   pitch AQP
    float* KV     = sm + 128*AQP;       // [64][128]       pitch AKP (K or V half)
    float* S      = KV + 64*AKP;        // [r 64][d 128]   pitch ASP (current chunk)
    float* m_s    = S + 64*ASP;         // [64] running max
    float* corr_s = m_s + 64;           // [64] rescale factor
    float* linv_s = corr_s + 64;        // [64] running sum -> 1/l

    const int q0 = blockIdx.x * 64;
    const int h = blockIdx.y, b = blockIdx.z;
    const int tid = threadIdx.x;
    const int tx = tid & 31, ty = tid >> 5;
    const float scale = 0.17677669529663687f;  // 1/sqrt(32)

    const int bh = b * H_ + h;
    const float* qb = q + bh * (W_ * C_);   // [w][c]
    const float* kb = k + bh * (W_ * C_);   // [w][c]
    const float* vb = v + bh * (C_ * W_);   // [c][w]

    // Q tile: Qt[w][r]  (gmem already [w][c])
    for (int idx = tid; idx < 128*16; idx += 256) {
        int w = idx >> 4, c4 = idx & 15;
        *(float4*)&Qt[w*AQP + c4*4] = *(const float4*)(qb + w*C_ + q0 + c4*4);
    }

    ull oacc2[8][2];
    #pragma unroll
    for (int i = 0; i < 8; i++) { oacc2[i][0]=0ULL; oacc2[i][1]=0ULL; }

    for (int dt = 0; dt < 2; dt++) {
        // ---- S chunk = scale * Q K^T  (d cols dt*128..+127), w in halves ----
        ull sacc2[4][4];
        #pragma unroll
        for (int p = 0; p < 4; p++) { sacc2[p][0]=0ULL; sacc2[p][1]=0ULL; sacc2[p][2]=0ULL; sacc2[p][3]=0ULL; }

        for (int wh = 0; wh < 2; wh++) {
            __syncthreads();
            for (int idx = tid; idx < 64*32; idx += 256) {
                int wl = idx >> 5, d4 = idx & 31;
                *(float4*)&KV[wl*AKP + d4*4] =
                    *(const float4*)(kb + (wh*64 + wl)*C_ + dt*128 + d4*4);
            }
            __syncthreads();
            #pragma unroll 2
            for (int wl = 0; wl < 64; wl++) {
                const ull* qp = (const ull*)&Qt[(wh*64 + wl)*AQP + ty*8];  // 4 row-pairs (broadcast)
                float4 kf = *(const float4*)&KV[wl*AKP + tx*4];            // conflict-free
                ull b0 = pack2(kf.x), b1 = pack2(kf.y), b2 = pack2(kf.z), b3 = pack2(kf.w);
                #pragma unroll
                for (int p = 0; p < 4; p++) {
                    ull a = qp[p];
                    ffma2(sacc2[p][0], a, b0);
                    ffma2(sacc2[p][1], a, b1);
                    ffma2(sacc2[p][2], a, b2);
                    ffma2(sacc2[p][3], a, b3);
                }
            }
        }
        // write scaled S chunk
        {
            ull sc2 = pack2(scale);
            #pragma unroll
            for (int p = 0; p < 4; p++) {
                float2 f0 = unpack2(mul2(sacc2[p][0], sc2));
                float2 f1 = unpack2(mul2(sacc2[p][1], sc2));
                float2 f2 = unpack2(mul2(sacc2[p][2], sc2));
                float2 f3 = unpack2(mul2(sacc2[p][3], sc2));
                int r0 = ty*8 + 2*p;
                *(float4*)&S[r0*ASP + tx*4]     = make_float4(f0.x, f1.x, f2.x, f3.x);
                *(float4*)&S[(r0+1)*ASP + tx*4] = make_float4(f0.y, f1.y, f2.y, f3.y);
            }
        }
        __syncthreads();

        // ---- online softmax on this chunk: 4 threads per row, 32 cols each ----
        {
            int r = tid >> 2, qq = tid & 3;
            float* srow = S + r*ASP + qq*32;
            float mc = -1e30f;
            #pragma unroll 8
            for (int j = 0; j < 32; j++) mc = fmaxf(mc, srow[j]);
            mc = fmaxf(mc, __shfl_xor_sync(0xffffffffu, mc, 1));
            mc = fmaxf(mc, __shfl_xor_sync(0xffffffffu, mc, 2));
            float m_old = (dt == 0) ? -1e30f : m_s[r];
            float m_new = fmaxf(m_old, mc);
            float l = 0.f;
            #pragma unroll 8
            for (int j = 0; j < 32; j++) { float e = __expf(srow[j] - m_new); srow[j] = e; l += e; }
            l += __shfl_xor_sync(0xffffffffu, l, 1);
            l += __shfl_xor_sync(0xffffffffu, l, 2);
            if (qq == 0) {
                if (dt == 0) { m_s[r] = m_new; linv_s[r] = l; corr_s[r] = 1.f; }
                else {
                    float corr = __expf(m_old - m_new);
                    corr_s[r] = corr;
                    linv_s[r] = 1.f / (linv_s[r] * corr + l);
                }
            }
        }
        __syncthreads();

        // rescale running O by correction (dt==1 only)
        if (dt == 1) {
            #pragma unroll
            for (int i = 0; i < 8; i++) {
                ull c2 = pack2(corr_s[ty*8 + i]);
                oacc2[i][0] = mul2(oacc2[i][0], c2);
                oacc2[i][1] = mul2(oacc2[i][1], c2);
            }
        }

        // ---- O += P V chunk, V rows (d) in halves ----
        for (int dh = 0; dh < 2; dh++) {
            __syncthreads();
            for (int idx = tid; idx < 64*32; idx += 256) {
                int dl = idx >> 5, w4 = idx & 31;
                *(float4*)&KV[dl*AKP + w4*4] =
                    *(const float4*)(vb + (dt*128 + dh*64 + dl)*W_ + w4*4);
            }
            __syncthreads();
            for (int d4 = 0; d4 < 64; d4 += 4) {
                float4 pf[8];
                #pragma unroll
                for (int i = 0; i < 8; i++)
                    pf[i] = *(const float4*)&S[(ty*8 + i)*ASP + dh*64 + d4];  // broadcast
                #pragma unroll
                for (int dd = 0; dd < 4; dd++) {
                    const ull* vp = (const ull*)&KV[(d4+dd)*AKP + tx*4];       // conflict-free
                    ull v0 = vp[0], v1 = vp[1];
                    #pragma unroll
                    for (int i = 0; i < 8; i++) {
                        float p = (dd==0) ? pf[i].x : (dd==1) ? pf[i].y : (dd==2) ? pf[i].z : pf[i].w;
                        ull p2 = pack2(p);
                        ffma2(oacc2[i][0], p2, v0);
                        ffma2(oacc2[i][1], p2, v1);
                    }
                }
            }
        }
    }

    // ---- epilogue ----
    #pragma unroll
    for (int i = 0; i < 8; i++) {
        float inv = linv_s[ty*8 + i];
        int cc = q0 + ty*8 + i;
        float2 o0 = unpack2(oacc2[i][0]);
        float2 o1 = unpack2(oacc2[i][1]);
        float4 v4 = make_float4(o0.x*inv, o0.y*inv, o1.x*inv, o1.y*inv);
        *(float4*)(out + ((b*C_ + cc)*H_ + h)*W_ + tx*4) = v4;
    }
}

// ---------------------------------------------------------------------------
extern "C" void kernel_launch(void* const* d_in, const int* in_sizes, int n_in,
                              void* d_out, int out_size)
{
    (void)in_sizes; (void)n_in; (void)out_size;
    const float* hidden = (const float*)d_in[0];
    const float* ctx    = (const float*)d_in[1];
    const float* qdw = (const float*)d_in[2];
    const float* qdb = (const float*)d_in[3];
    const float* qpw = (const float*)d_in[4];
    const float* qpb = (const float*)d_in[5];
    const float* kdw = (const float*)d_in[6];
    const float* kdb = (const float*)d_in[7];
    const float* kpw = (const float*)d_in[8];
    const float* kpb = (const float*)d_in[9];
    const float* vdw = (const float*)d_in[10];
    const float* vdb = (const float*)d_in[11];
    const float* vpw = (const float*)d_in[12];
    const float* vpb = (const float*)d_in[13];
    float* out = (float*)d_out;

    float *tmp, *qp, *kp, *vp;
    cudaGetSymbolAddress((void**)&tmp, g_tmp);
    cudaGetSymbolAddress((void**)&qp,  g_q);
    cudaGetSymbolAddress((void**)&kp,  g_k);
    cudaGetSymbolAddress((void**)&vp,  g_v);

    cudaFuncSetAttribute(attn_kernel, cudaFuncAttributeMaxDynamicSharedMemorySize, ATT_SMEM);

    dim3 dwg(H_, C_, B_);
    dim3 pwg(2, H_, B_);
    dim3 atg(4, H_, B_);

    dw_kernel<<<dwg, 128>>>(hidden, qdw, qdb, tmp);
    pw_kernel<1><<<pwg, 256>>>(tmp, qpw, qpb, qp);   // q -> [b][h][w][c]
    dw_kernel<<<dwg, 128>>>(ctx, kdw, kdb, tmp);
    pw_kernel<1><<<pwg, 256>>>(tmp, kpw, kpb, kp);   // k -> [b][h][w][c]
    dw_kernel<<<dwg, 128>>>(ctx, vdw, vdb, tmp);
    pw_kernel<0><<<pwg, 256>>>(tmp, vpw, vpb, vp);   // v -> [b][h][c][w]
    attn_kernel<<<atg, 256, ATT_SMEM>>>(qp, kp, vp, out);
}

// round 6
// speedup vs baseline: 2.0790x; 1.1489x over previous
#include <cuda_runtime.h>
#include <cstdint>

#define B_ 8
#define C_ 256
#define H_ 128
#define W_ 128
#define NEL (B_*C_*H_*W_)

// Scratch (no allocation allowed -> __device__ globals)
__device__ float g_tmp[NEL];
__device__ float g_q[NEL];           // [b][h][w][c]
__device__ float g_k[NEL];           // [b][h][w][c]
__device__ float g_v[NEL];           // [b][h][c][w]
__device__ float g_wt[3 * C_ * C_];  // transposed pw weights Wt[c][o], q/k/v

typedef unsigned long long ull;

// ---- packed fp32x2 helpers (FFMA2) ----
__device__ __forceinline__ void ffma2(ull& d, ull a, ull b) {
    asm("fma.rn.f32x2 %0, %1, %2, %3;" : "=l"(d) : "l"(a), "l"(b), "l"(d));
}
__device__ __forceinline__ ull mul2(ull a, ull b) {
    ull r; asm("mul.rn.f32x2 %0, %1, %2;" : "=l"(r) : "l"(a), "l"(b)); return r;
}
__device__ __forceinline__ ull pack2(float x) {
    ull r; asm("mov.b64 %0, {%1, %1};" : "=l"(r) : "f"(x)); return r;
}
__device__ __forceinline__ float2 unpack2(ull a) {
    float2 f; asm("mov.b64 {%0, %1}, %2;" : "=f"(f.x), "=f"(f.y) : "l"(a)); return f;
}

// ---- cp.async helpers ----
__device__ __forceinline__ uint32_t saddr(const void* p) {
    return (uint32_t)__cvta_generic_to_shared(p);
}
__device__ __forceinline__ void cp16(uint32_t dst, const void* src) {
    asm volatile("cp.async.cg.shared.global [%0], [%1], 16;" :: "r"(dst), "l"(src));
}
#define CP_COMMIT asm volatile("cp.async.commit_group;")
#define CP_WAIT0  asm volatile("cp.async.wait_group 0;")

// ---------------------------------------------------------------------------
// 256x256 weight transpose: Wt[c][o] = W[o][c].  grid (8,8), block (32,8).
// ---------------------------------------------------------------------------
__global__ void wt_kernel(const float* __restrict__ W, float* __restrict__ Wt)
{
    __shared__ float tile[32][33];
    const int x0 = blockIdx.x * 32, y0 = blockIdx.y * 32;
    const int tx = threadIdx.x, ty = threadIdx.y;
    #pragma unroll
    for (int j = 0; j < 32; j += 8)
        tile[ty + j][tx] = W[(y0 + ty + j) * C_ + x0 + tx];
    __syncthreads();
    #pragma unroll
    for (int j = 0; j < 32; j += 8)
        Wt[(x0 + ty + j) * C_ + y0 + tx] = tile[tx][ty + j];
}

// ---------------------------------------------------------------------------
// Depthwise 3x3 (SAME) + bias, 4 outputs/thread.  grid (H/4, C, B), block (32,4)
// ---------------------------------------------------------------------------
__global__ __launch_bounds__(128) void dw_kernel(
    const float* __restrict__ x, const float* __restrict__ wgt,
    const float* __restrict__ bias, float* __restrict__ out)
{
    const int c = blockIdx.y, b = blockIdx.z;
    const int h = blockIdx.x * 4 + threadIdx.y;
    const int w0 = threadIdx.x * 4;
    const float* wc = wgt + c * 9;
    const float* plane = x + (b * C_ + c) * (H_ * W_);
    float bv = __ldg(&bias[c]);
    float4 acc = make_float4(bv, bv, bv, bv);
    #pragma unroll
    for (int i = 0; i < 3; i++) {
        int hh = h + i - 1;
        if (hh < 0 || hh >= H_) continue;
        const float* row = plane + hh * W_;
        float4 xc = *(const float4*)(row + w0);
        float xl = (w0 > 0)        ? __ldg(&row[w0 - 1]) : 0.f;
        float xr = (w0 + 4 < W_)   ? __ldg(&row[w0 + 4]) : 0.f;
        float wl = __ldg(&wc[i*3+0]), wm = __ldg(&wc[i*3+1]), wr = __ldg(&wc[i*3+2]);
        acc.x += wl*xl   + wm*xc.x + wr*xc.y;
        acc.y += wl*xc.x + wm*xc.y + wr*xc.z;
        acc.z += wl*xc.y + wm*xc.z + wr*xc.w;
        acc.w += wl*xc.z + wm*xc.w + wr*xr;
    }
    *(float4*)(out + (b * C_ + c) * (H_*W_) + h * W_ + w0) = acc;
}

// ---------------------------------------------------------------------------
// Pointwise 1x1 GEMM, FFMA2 + cp.async double-buffered tiles.
// CTA 128(o) x 128(w), 256 threads, thread tile 16(o) x 4(w).
// Wt is PRE-TRANSPOSED [c][o] so the A tile is a contiguous cp.async copy.
// ---------------------------------------------------------------------------
#define PW_AP 132
#define PW_BP 132

template<int TRANS>
__global__ __launch_bounds__(256, 2) void pw_kernel(
    const float* __restrict__ t, const float* __restrict__ Wt,
    const float* __restrict__ bias, float* __restrict__ out)
{
    __shared__ float At[2][16 * PW_AP];
    __shared__ float Bs[2][16 * PW_BP];
    const int o0 = blockIdx.x * 128;
    const int h = blockIdx.y, b = blockIdx.z;
    const int tid = threadIdx.x;
    const int tx = tid & 31, ty = tid >> 5;

    ull acc2[8][4];
    #pragma unroll
    for (int p = 0; p < 8; p++) { acc2[p][0]=0ULL; acc2[p][1]=0ULL; acc2[p][2]=0ULL; acc2[p][3]=0ULL; }

    const int cl = tid >> 4;            // 0..15 (c row within tile)
    const int e8 = (tid & 15) * 8;      // 8-float chunk within row
    const float* tb = t + b * (C_ * H_ * W_) + h * W_;

    // tile loader: A row = Wt[kk+cl][o0+e8..+7], B row = t[kk+cl][h][e8..+7]
    #define PW_LOAD(kk, buf) do { \
        const float* wr = Wt + (kk + cl) * C_ + o0 + e8; \
        cp16(saddr(&At[buf][cl*PW_AP + e8]),     wr); \
        cp16(saddr(&At[buf][cl*PW_AP + e8 + 4]), wr + 4); \
        const float* br = tb + (kk + cl) * (H_ * W_) + e8; \
        cp16(saddr(&Bs[buf][cl*PW_BP + e8]),     br); \
        cp16(saddr(&Bs[buf][cl*PW_BP + e8 + 4]), br + 4); \
    } while (0)

    PW_LOAD(0, 0); CP_COMMIT; CP_WAIT0; __syncthreads();

    for (int t16 = 0; t16 < 16; t16++) {
        if (t16 < 15) { PW_LOAD((t16+1)*16, (t16+1)&1); CP_COMMIT; }
        const float* at = At[t16 & 1];
        const float* bs = Bs[t16 & 1];
        #pragma unroll
        for (int c = 0; c < 16; c++) {
            const ull* ar = (const ull*)&at[c*PW_AP + ty*16];   // 8 o-pairs (broadcast)
            float4 bf = *(const float4*)&bs[c*PW_BP + tx*4];    // conflict-free
            ull b0 = pack2(bf.x), b1 = pack2(bf.y), b2 = pack2(bf.z), b3 = pack2(bf.w);
            #pragma unroll
            for (int p = 0; p < 8; p++) {
                ull a = ar[p];
                ffma2(acc2[p][0], a, b0);
                ffma2(acc2[p][1], a, b1);
                ffma2(acc2[p][2], a, b2);
                ffma2(acc2[p][3], a, b3);
            }
        }
        if (t16 < 15) { CP_WAIT0; __syncthreads(); }
    }
    #undef PW_LOAD

    float bo[16];
    #pragma unroll
    for (int i = 0; i < 16; i++) bo[i] = __ldg(&bias[o0 + ty*16 + i]);

    if (TRANS) {
        float* ob = out + (b * H_ + h) * (W_ * C_);
        #pragma unroll
        for (int j = 0; j < 4; j++) {
            float* op = ob + (tx*4 + j) * C_ + o0 + ty*16;
            #pragma unroll
            for (int p4 = 0; p4 < 4; p4++) {
                float2 e0 = unpack2(acc2[p4*2][j]);
                float2 e1 = unpack2(acc2[p4*2+1][j]);
                float4 v4 = make_float4(e0.x + bo[p4*4+0], e0.y + bo[p4*4+1],
                                        e1.x + bo[p4*4+2], e1.y + bo[p4*4+3]);
                *(float4*)(op + p4*4) = v4;
            }
        }
    } else {
        float* ob = out + ((b * H_ + h) * C_ + o0 + ty*16) * W_ + tx*4;
        #pragma unroll
        for (int p = 0; p < 8; p++) {
            float2 f0 = unpack2(acc2[p][0]);
            float2 f1 = unpack2(acc2[p][1]);
            float2 f2 = unpack2(acc2[p][2]);
            float2 f3 = unpack2(acc2[p][3]);
            float blo = bo[2*p], bhi = bo[2*p+1];
            *(float4*)(ob + (2*p)*W_)   = make_float4(f0.x+blo, f1.x+blo, f2.x+blo, f3.x+blo);
            *(float4*)(ob + (2*p+1)*W_) = make_float4(f0.y+bhi, f1.y+bhi, f2.y+bhi, f3.y+bhi);
        }
    }
}

// ---------------------------------------------------------------------------
// Attention: one CTA of 512 threads per (b, h, 128-row q tile).
// Online softmax over two 128-wide d chunks.  K/V streamed through two
// 64x128 buffers with cp.async double-buffering; V-half prefetch overlaps
// softmax; K(dt=1) prefetch overlaps last PV half of dt=0.
// ---------------------------------------------------------------------------
#define AQP 132
#define AKP 132
#define ASP 132
#define ATT_SMEM ((128*AQP + 2*64*AKP + 128*ASP + 3*128) * 4)

__global__ __launch_bounds__(512, 1) void attn_kernel(
    const float* __restrict__ q, const float* __restrict__ k,
    const float* __restrict__ v, float* __restrict__ out)
{
    extern __shared__ float sm[];
    float* Qt     = sm;                   // [w 128][r 128]
    float* KV0    = sm + 128*AQP;         // [64][128]
    float* KV1    = KV0 + 64*AKP;         // [64][128]
    float* S      = KV1 + 64*AKP;         // [r 128][d 128] current chunk
    float* m_s    = S + 128*ASP;          // [128]
    float* corr_s = m_s + 128;            // [128]
    float* linv_s = corr_s + 128;         // [128]

    const int q0 = blockIdx.x * 128;
    const int h = blockIdx.y, b = blockIdx.z;
    const int tid = threadIdx.x;
    const int tx = tid & 31, ty = tid >> 5;     // ty 0..15
    const float scale = 0.17677669529663687f;   // 1/sqrt(32)

    const int bh = b * H_ + h;
    const float* qb = q + bh * (W_ * C_);   // [w][c]
    const float* kb = k + bh * (W_ * C_);   // [w][c]
    const float* vb = v + bh * (C_ * W_);   // [c][w]

    // Q tile: Qt[w][r]
    for (int idx = tid; idx < 128*32; idx += 512) {
        int w = idx >> 5, c4 = idx & 31;
        *(float4*)&Qt[w*AQP + c4*4] = *(const float4*)(qb + w*C_ + q0 + c4*4);
    }

    // cp.async loaders for a 64x128 block (4 chunks per thread)
    #define LOAD_K(dst, woff, doff) do { \
        for (int idx = tid; idx < 64*32; idx += 512) { \
            int wl = idx >> 5, d4 = idx & 31; \
            cp16(saddr(&(dst)[wl*AKP + d4*4]), kb + ((woff)+wl)*C_ + (doff) + d4*4); \
        } } while (0)
    #define LOAD_V(dst, coff) do { \
        for (int idx = tid; idx < 64*32; idx += 512) { \
            int dl = idx >> 5, w4 = idx & 31; \
            cp16(saddr(&(dst)[dl*AKP + w4*4]), vb + ((coff)+dl)*W_ + w4*4); \
        } } while (0)

    ull oacc2[8][2];
    #pragma unroll
    for (int i = 0; i < 8; i++) { oacc2[i][0]=0ULL; oacc2[i][1]=0ULL; }

    LOAD_K(KV0, 0, 0); CP_COMMIT; CP_WAIT0; __syncthreads();

    for (int dt = 0; dt < 2; dt++) {
        ull sacc2[4][4];
        #pragma unroll
        for (int p = 0; p < 4; p++) { sacc2[p][0]=0ULL; sacc2[p][1]=0ULL; sacc2[p][2]=0ULL; sacc2[p][3]=0ULL; }

        // ---- S += Q·K, half wh=0 on KV0, prefetch K half1 -> KV1 ----
        LOAD_K(KV1, 64, dt*128); CP_COMMIT;
        #pragma unroll 2
        for (int wl = 0; wl < 64; wl++) {
            const ull* qp = (const ull*)&Qt[wl*AQP + ty*8];
            float4 kf = *(const float4*)&KV0[wl*AKP + tx*4];
            ull b0 = pack2(kf.x), b1 = pack2(kf.y), b2 = pack2(kf.z), b3 = pack2(kf.w);
            #pragma unroll
            for (int p = 0; p < 4; p++) {
                ull a = qp[p];
                ffma2(sacc2[p][0], a, b0);
                ffma2(sacc2[p][1], a, b1);
                ffma2(sacc2[p][2], a, b2);
                ffma2(sacc2[p][3], a, b3);
            }
        }
        CP_WAIT0; __syncthreads();

        // ---- half wh=1 on KV1, prefetch V half0 -> KV0 ----
        LOAD_V(KV0, dt*128); CP_COMMIT;
        #pragma unroll 2
        for (int wl = 0; wl < 64; wl++) {
            const ull* qp = (const ull*)&Qt[(64+wl)*AQP + ty*8];
            float4 kf = *(const float4*)&KV1[wl*AKP + tx*4];
            ull b0 = pack2(kf.x), b1 = pack2(kf.y), b2 = pack2(kf.z), b3 = pack2(kf.w);
            #pragma unroll
            for (int p = 0; p < 4; p++) {
                ull a = qp[p];
                ffma2(sacc2[p][0], a, b0);
                ffma2(sacc2[p][1], a, b1);
                ffma2(sacc2[p][2], a, b2);
                ffma2(sacc2[p][3], a, b3);
            }
        }
        // write scaled S chunk
        {
            ull sc2 = pack2(scale);
            #pragma unroll
            for (int p = 0; p < 4; p++) {
                float2 f0 = unpack2(mul2(sacc2[p][0], sc2));
                float2 f1 = unpack2(mul2(sacc2[p][1], sc2));
                float2 f2 = unpack2(mul2(sacc2[p][2], sc2));
                float2 f3 = unpack2(mul2(sacc2[p][3], sc2));
                int r0 = ty*8 + 2*p;
                *(float4*)&S[r0*ASP + tx*4]     = make_float4(f0.x, f1.x, f2.x, f3.x);
                *(float4*)&S[(r0+1)*ASP + tx*4] = make_float4(f0.y, f1.y, f2.y, f3.y);
            }
        }
        CP_WAIT0; __syncthreads();

        // ---- softmax (online), prefetch V half1 -> KV1 during it ----
        LOAD_V(KV1, dt*128 + 64); CP_COMMIT;
        {
            int r = tid >> 2, qq = tid & 3;
            float* srow = S + r*ASP + qq*32;
            float mc = -1e30f;
            #pragma unroll 8
            for (int j = 0; j < 32; j++) mc = fmaxf(mc, srow[j]);
            mc = fmaxf(mc, __shfl_xor_sync(0xffffffffu, mc, 1));
            mc = fmaxf(mc, __shfl_xor_sync(0xffffffffu, mc, 2));
            float m_old = (dt == 0) ? -1e30f : m_s[r];
            float m_new = fmaxf(m_old, mc);
            float l = 0.f;
            #pragma unroll 8
            for (int j = 0; j < 32; j++) { float e = __expf(srow[j] - m_new); srow[j] = e; l += e; }
            l += __shfl_xor_sync(0xffffffffu, l, 1);
            l += __shfl_xor_sync(0xffffffffu, l, 2);
            if (qq == 0) {
                if (dt == 0) { m_s[r] = m_new; linv_s[r] = l; corr_s[r] = 1.f; }
                else {
                    float corr = __expf(m_old - m_new);
                    m_s[r] = m_new;
                    corr_s[r] = corr;
                    linv_s[r] = 1.f / (linv_s[r] * corr + l);
                }
            }
        }
        CP_WAIT0; __syncthreads();

        // rescale running O (dt==1 only)
        if (dt == 1) {
            #pragma unroll
            for (int i = 0; i < 8; i++) {
                ull c2 = pack2(corr_s[ty*8 + i]);
                oacc2[i][0] = mul2(oacc2[i][0], c2);
                oacc2[i][1] = mul2(oacc2[i][1], c2);
            }
        }

        // ---- O += P·V, half dh=0 on KV0 ----
        for (int d4 = 0; d4 < 64; d4 += 4) {
            float4 pf[8];
            #pragma unroll
            for (int i = 0; i < 8; i++)
                pf[i] = *(const float4*)&S[(ty*8 + i)*ASP + d4];
            #pragma unroll
            for (int dd = 0; dd < 4; dd++) {
                const ull* vp = (const ull*)&KV0[(d4+dd)*AKP + tx*4];
                ull v0 = vp[0], v1 = vp[1];
                #pragma unroll
                for (int i = 0; i < 8; i++) {
                    float p = (dd==0) ? pf[i].x : (dd==1) ? pf[i].y : (dd==2) ? pf[i].z : pf[i].w;
                    ull p2 = pack2(p);
                    ffma2(oacc2[i][0], p2, v0);
                    ffma2(oacc2[i][1], p2, v1);
                }
            }
        }
        __syncthreads();   // KV0 free for next prefetch

        // ---- half dh=1 on KV1, prefetch K(dt=1, half0) -> KV0 ----
        if (dt == 0) { LOAD_K(KV0, 0, 128); CP_COMMIT; }
        for (int d4 = 0; d4 < 64; d4 += 4) {
            float4 pf[8];
            #pragma unroll
            for (int i = 0; i < 8; i++)
                pf[i] = *(const float4*)&S[(ty*8 + i)*ASP + 64 + d4];
            #pragma unroll
            for (int dd = 0; dd < 4; dd++) {
                const ull* vp = (const ull*)&KV1[(d4+dd)*AKP + tx*4];
                ull v0 = vp[0], v1 = vp[1];
                #pragma unroll
                for (int i = 0; i < 8; i++) {
                    float p = (dd==0) ? pf[i].x : (dd==1) ? pf[i].y : (dd==2) ? pf[i].z : pf[i].w;
                    ull p2 = pack2(p);
                    ffma2(oacc2[i][0], p2, v0);
                    ffma2(oacc2[i][1], p2, v1);
                }
            }
        }
        if (dt == 0) { CP_WAIT0; __syncthreads(); }
    }
    #undef LOAD_K
    #undef LOAD_V

    // ---- epilogue ----
    #pragma unroll
    for (int i = 0; i < 8; i++) {
        float inv = linv_s[ty*8 + i];
        int cc = q0 + ty*8 + i;
        float2 o0 = unpack2(oacc2[i][0]);
        float2 o1 = unpack2(oacc2[i][1]);
        float4 v4 = make_float4(o0.x*inv, o0.y*inv, o1.x*inv, o1.y*inv);
        *(float4*)(out + ((b*C_ + cc)*H_ + h)*W_ + tx*4) = v4;
    }
}

// ---------------------------------------------------------------------------
extern "C" void kernel_launch(void* const* d_in, const int* in_sizes, int n_in,
                              void* d_out, int out_size)
{
    (void)in_sizes; (void)n_in; (void)out_size;
    const float* hidden = (const float*)d_in[0];
    const float* ctx    = (const float*)d_in[1];
    const float* qdw = (const float*)d_in[2];
    const float* qdb = (const float*)d_in[3];
    const float* qpw = (const float*)d_in[4];
    const float* qpb = (const float*)d_in[5];
    const float* kdw = (const float*)d_in[6];
    const float* kdb = (const float*)d_in[7];
    const float* kpw = (const float*)d_in[8];
    const float* kpb = (const float*)d_in[9];
    const float* vdw = (const float*)d_in[10];
    const float* vdb = (const float*)d_in[11];
    const float* vpw = (const float*)d_in[12];
    const float* vpb = (const float*)d_in[13];
    float* out = (float*)d_out;

    float *tmp, *qp, *kp, *vp, *wt;
    cudaGetSymbolAddress((void**)&tmp, g_tmp);
    cudaGetSymbolAddress((void**)&qp,  g_q);
    cudaGetSymbolAddress((void**)&kp,  g_k);
    cudaGetSymbolAddress((void**)&vp,  g_v);
    cudaGetSymbolAddress((void**)&wt,  g_wt);
    float* wtq = wt;
    float* wtk = wt + C_*C_;
    float* wtv = wt + 2*C_*C_;

    cudaFuncSetAttribute(attn_kernel, cudaFuncAttributeMaxDynamicSharedMemorySize, ATT_SMEM);

    dim3 wtg(8, 8);
    dim3 wtb(32, 8);
    dim3 dwg(H_/4, C_, B_);
    dim3 dwb(32, 4);
    dim3 pwg(2, H_, B_);
    dim3 atg(2, H_, B_);

    wt_kernel<<<wtg, wtb>>>(qpw, wtq);
    wt_kernel<<<wtg, wtb>>>(kpw, wtk);
    wt_kernel<<<wtg, wtb>>>(vpw, wtv);

    dw_kernel<<<dwg, dwb>>>(hidden, qdw, qdb, tmp);
    pw_kernel<1><<<pwg, 256>>>(tmp, wtq, qpb, qp);   // q -> [b][h][w][c]
    dw_kernel<<<dwg, dwb>>>(ctx, kdw, kdb, tmp);
    pw_kernel<1><<<pwg, 256>>>(tmp, wtk, kpb, kp);   // k -> [b][h][w][c]
    dw_kernel<<<dwg, dwb>>>(ctx, vdw, vdb, tmp);
    pw_kernel<0><<<pwg, 256>>>(tmp, wtv, vpb, vp);   // v -> [b][h][c][w]
    attn_kernel<<<atg, 512, ATT_SMEM>>>(qp, kp, vp, out);
}

// round 8
// speedup vs baseline: 2.4103x; 1.1594x over previous
#include <cuda_runtime.h>
#include <cuda_bf16.h>
#include <cstdint>

#define B_ 8
#define C_ 256
#define H_ 128
#define W_ 128
#define NEL (B_*C_*H_*W_)

// Scratch (no allocation allowed -> __device__ globals)
__device__ float g_tmp[NEL];
__device__ float g_q[NEL];                     // [b][h][w][c] fp32
__device__ float g_k[NEL];                     // [b][h][w][c] fp32
__device__ float g_v[NEL];                     // [b][h][c][w] fp32
__device__ __nv_bfloat16 g_whi[3 * C_ * C_];   // weight hi, K-major [o][c]
__device__ __nv_bfloat16 g_wlo[3 * C_ * C_];   // weight lo
__device__ __nv_bfloat16 g_thi[NEL];           // activation hi, [b][h][w][c]
__device__ __nv_bfloat16 g_tlo[NEL];           // activation lo

typedef unsigned long long ull;

// ---- packed fp32x2 helpers (FFMA2) ----
__device__ __forceinline__ void ffma2(ull& d, ull a, ull b) {
    asm("fma.rn.f32x2 %0, %1, %2, %3;" : "=l"(d) : "l"(a), "l"(b), "l"(d));
}
__device__ __forceinline__ ull mul2(ull a, ull b) {
    ull r; asm("mul.rn.f32x2 %0, %1, %2;" : "=l"(r) : "l"(a), "l"(b)); return r;
}
__device__ __forceinline__ ull pack2(float x) {
    ull r; asm("mov.b64 %0, {%1, %1};" : "=l"(r) : "f"(x)); return r;
}
__device__ __forceinline__ float2 unpack2(ull a) {
    float2 f; asm("mov.b64 {%0, %1}, %2;" : "=f"(f.x), "=f"(f.y) : "l"(a)); return f;
}

// ---- cp.async helpers ----
__device__ __forceinline__ uint32_t saddr(const void* p) {
    return (uint32_t)__cvta_generic_to_shared(p);
}
__device__ __forceinline__ void cp16(uint32_t dst, const void* src) {
    asm volatile("cp.async.cg.shared.global [%0], [%1], 16;" :: "r"(dst), "l"(src));
}
#define CP_COMMIT asm volatile("cp.async.commit_group;")
#define CP_WAIT0  asm volatile("cp.async.wait_group 0;")

// ---- mma.sync / ldmatrix helpers (plain sm_103 features, no 'a' needed) ----
__device__ __forceinline__ void ldmx4(uint32_t* r, uint32_t addr) {
    asm volatile("ldmatrix.sync.aligned.m8n8.x4.shared.b16 {%0,%1,%2,%3}, [%4];"
                 : "=r"(r[0]), "=r"(r[1]), "=r"(r[2]), "=r"(r[3]) : "r"(addr));
}
__device__ __forceinline__ void mma16816(float* d, const uint32_t* a, const uint32_t* b) {
    asm volatile(
        "mma.sync.aligned.m16n8k16.row.col.f32.bf16.bf16.f32 "
        "{%0,%1,%2,%3}, {%4,%5,%6,%7}, {%8,%9}, {%0,%1,%2,%3};"
        : "+f"(d[0]), "+f"(d[1]), "+f"(d[2]), "+f"(d[3])
        : "r"(a[0]), "r"(a[1]), "r"(a[2]), "r"(a[3]), "r"(b[0]), "r"(b[1]));
}

// ---------------------------------------------------------------------------
// Weight split: W[o][c] fp32 -> hi/lo bf16 (K-major, layout unchanged)
// ---------------------------------------------------------------------------
__global__ void wsplit_kernel(const float* __restrict__ W,
                              __nv_bfloat16* __restrict__ hi,
                              __nv_bfloat16* __restrict__ lo)
{
    int i = blockIdx.x * 256 + threadIdx.x;
    float x = W[i];
    __nv_bfloat16 h = __float2bfloat16_rn(x);
    hi[i] = h;
    lo[i] = __float2bfloat16_rn(x - __bfloat162float(h));
}

// ---------------------------------------------------------------------------
// Activation split + transpose: t[b][c][h][w] fp32 -> hi/lo [b][h][w][c] bf16
// grid (W/32, C/32, B*H), block (32,8)
// ---------------------------------------------------------------------------
__global__ void asplit_kernel(const float* __restrict__ t,
                              __nv_bfloat16* __restrict__ hi,
                              __nv_bfloat16* __restrict__ lo)
{
    __shared__ float tile[32][33];
    const int bz = blockIdx.z;           // b*H + h
    const int b = bz >> 7, h = bz & 127;
    const int w0 = blockIdx.x * 32, c0 = blockIdx.y * 32;
    const int tx = threadIdx.x, ty = threadIdx.y;
    #pragma unroll
    for (int j = 0; j < 32; j += 8)
        tile[ty + j][tx] = t[((b * C_ + c0 + ty + j) * H_ + h) * W_ + w0 + tx];
    __syncthreads();
    #pragma unroll
    for (int j = 0; j < 32; j += 8) {
        float x = tile[tx][ty + j];                      // c = c0+tx, w = w0+ty+j
        __nv_bfloat16 hh = __float2bfloat16_rn(x);
        __nv_bfloat16 ll = __float2bfloat16_rn(x - __bfloat162float(hh));
        int idx = (bz * W_ + w0 + ty + j) * C_ + c0 + tx;
        hi[idx] = hh;
        lo[idx] = ll;
    }
}

// ---------------------------------------------------------------------------
// Depthwise 3x3 (SAME) + bias, 4 outputs/thread.  grid (H/4, C, B), block (32,4)
// ---------------------------------------------------------------------------
__global__ __launch_bounds__(128) void dw_kernel(
    const float* __restrict__ x, const float* __restrict__ wgt,
    const float* __restrict__ bias, float* __restrict__ out)
{
    const int c = blockIdx.y, b = blockIdx.z;
    const int h = blockIdx.x * 4 + threadIdx.y;
    const int w0 = threadIdx.x * 4;
    const float* wc = wgt + c * 9;
    const float* plane = x + (b * C_ + c) * (H_ * W_);
    float bv = __ldg(&bias[c]);
    float4 acc = make_float4(bv, bv, bv, bv);
    #pragma unroll
    for (int i = 0; i < 3; i++) {
        int hh = h + i - 1;
        if (hh < 0 || hh >= H_) continue;
        const float* row = plane + hh * W_;
        float4 xc = *(const float4*)(row + w0);
        float xl = (w0 > 0)        ? __ldg(&row[w0 - 1]) : 0.f;
        float xr = (w0 + 4 < W_)   ? __ldg(&row[w0 + 4]) : 0.f;
        float wl = __ldg(&wc[i*3+0]), wm = __ldg(&wc[i*3+1]), wr = __ldg(&wc[i*3+2]);
        acc.x += wl*xl   + wm*xc.x + wr*xc.y;
        acc.y += wl*xc.x + wm*xc.y + wr*xc.z;
        acc.z += wl*xc.y + wm*xc.z + wr*xc.w;
        acc.w += wl*xc.z + wm*xc.w + wr*xr;
    }
    *(float4*)(out + (b * C_ + c) * (H_*W_) + h * W_ + w0) = acc;
}

// ---------------------------------------------------------------------------
// Pointwise 1x1 as mma.sync split-bf16 GEMM (HMMA fallback pipe).
// Per CTA: D[128 o][128 w] = sum_c W[o][c]*t[c][w] for one (b, h, o-tile).
// 256 threads = 8 warps in 2(o) x 4(w); warp tile 64x32; m16n8k16 atoms.
// K=256 staged in two 128 chunks; 3 products hi*hi + hi*lo + lo*hi.
// Both operands K-major => .row.col, plain (non-trans) ldmatrix for both.
// ---------------------------------------------------------------------------
#define MP 136                       // bf16 pitch (272B rows: 16B-aligned, conflict-free)
#define PW_AHI 0
#define PW_ALO (128*MP)
#define PW_BHI (2*128*MP)
#define PW_BLO (3*128*MP)
#define PWS_SMEM (4*128*MP*2)        // 139264 bytes

template<int TRANS>
__global__ __launch_bounds__(256, 1) void pw_mma_kernel(
    const __nv_bfloat16* __restrict__ thi, const __nv_bfloat16* __restrict__ tlo,
    const __nv_bfloat16* __restrict__ whi, const __nv_bfloat16* __restrict__ wlo,
    const float* __restrict__ bias, float* __restrict__ out)
{
    extern __shared__ char psm[];
    __nv_bfloat16* SB = (__nv_bfloat16*)psm;
    const uint32_t sbase = saddr(psm);
    const int o0 = blockIdx.x * 128;
    const int h = blockIdx.y, b = blockIdx.z;
    const int bh = b * H_ + h;
    const int tid = threadIdx.x;
    const int wid = tid >> 5, lane = tid & 31;
    const int m0 = (wid >> 2) * 64;      // warp o-offset (0/64)
    const int n0 = (wid & 3) * 32;       // warp w-offset (0/32/64/96)

    float d[4][4][4];
    #pragma unroll
    for (int mi = 0; mi < 4; mi++)
        #pragma unroll
        for (int ni = 0; ni < 4; ni++)
            { d[mi][ni][0]=0.f; d[mi][ni][1]=0.f; d[mi][ni][2]=0.f; d[mi][ni][3]=0.f; }

    // per-thread ldmatrix offsets (bf16 elements)
    int a_off[4], b_off[2];
    #pragma unroll
    for (int mi = 0; mi < 4; mi++)
        a_off[mi] = (m0 + mi*16 + (lane & 15)) * MP + (lane >> 4) * 8;
    #pragma unroll
    for (int p = 0; p < 2; p++) {
        int tl = lane >> 3;
        b_off[p] = (n0 + p*16 + (tl >> 1)*8 + (lane & 7)) * MP + (tl & 1) * 8;
    }

    const __nv_bfloat16* tbh = thi + (size_t)bh * (W_ * C_);
    const __nv_bfloat16* tbl = tlo + (size_t)bh * (W_ * C_);
    const int rl = tid >> 4, c8 = (tid & 15) * 8;   // stage mapping (8 uint4/thread/buffer)

    for (int ch = 0; ch < 2; ch++) {
        const int kk = ch * 128;
        __syncthreads();
        // stage 4 tiles [128][128] bf16 via cp.async
        #pragma unroll
        for (int rr = 0; rr < 8; rr++) {
            int r = rl + rr * 16;
            uint32_t doff = (uint32_t)(r * MP + c8) * 2;
            cp16(sbase + PW_AHI*2 + doff, whi + (o0 + r) * C_ + kk + c8);
            cp16(sbase + PW_ALO*2 + doff, wlo + (o0 + r) * C_ + kk + c8);
            cp16(sbase + PW_BHI*2 + doff, tbh + r * C_ + kk + c8);
            cp16(sbase + PW_BLO*2 + doff, tbl + r * C_ + kk + c8);
        }
        CP_COMMIT; CP_WAIT0; __syncthreads();

        #pragma unroll
        for (int ks = 0; ks < 8; ks++) {
            const int k0 = ks * 16;
            uint32_t ah[4][4], al[4][4], bh2[2][4], bl2[2][4];
            #pragma unroll
            for (int mi = 0; mi < 4; mi++) {
                ldmx4(ah[mi], sbase + (PW_AHI + a_off[mi] + k0) * 2);
                ldmx4(al[mi], sbase + (PW_ALO + a_off[mi] + k0) * 2);
            }
            #pragma unroll
            for (int p = 0; p < 2; p++) {
                ldmx4(bh2[p], sbase + (PW_BHI + b_off[p] + k0) * 2);
                ldmx4(bl2[p], sbase + (PW_BLO + b_off[p] + k0) * 2);
            }
            #pragma unroll
            for (int mi = 0; mi < 4; mi++)
                #pragma unroll
                for (int ni = 0; ni < 4; ni++) {
                    const uint32_t* bh_f = &bh2[ni >> 1][(ni & 1) * 2];
                    const uint32_t* bl_f = &bl2[ni >> 1][(ni & 1) * 2];
                    mma16816(d[mi][ni], ah[mi], bh_f);
                    mma16816(d[mi][ni], ah[mi], bl_f);
                    mma16816(d[mi][ni], al[mi], bh_f);
                }
        }
    }

    // ---- epilogue ----
    if (TRANS) {
        // transpose bounce through smem: DS[w(n)][o(m)] pitch 132 (conflict-free)
        __syncthreads();
        float* DS = (float*)psm;
        #pragma unroll
        for (int mi = 0; mi < 4; mi++) {
            int m_ = m0 + mi*16 + (lane >> 2);
            #pragma unroll
            for (int ni = 0; ni < 4; ni++) {
                int n_ = n0 + ni*8 + (lane & 3)*2;
                DS[n_*132 + m_]         = d[mi][ni][0];
                DS[(n_+1)*132 + m_]     = d[mi][ni][1];
                DS[n_*132 + m_ + 8]     = d[mi][ni][2];
                DS[(n_+1)*132 + m_ + 8] = d[mi][ni][3];
            }
        }
        __syncthreads();
        float* ob = out + (size_t)bh * (W_ * C_) + o0;
        for (int i = tid; i < 128*32; i += 256) {
            int w = i >> 5, o4 = (i & 31) * 4;
            float4 v = *(float4*)&DS[w*132 + o4];
            float4 bv = *(const float4*)&bias[o0 + o4];
            v.x += bv.x; v.y += bv.y; v.z += bv.z; v.w += bv.w;
            *(float4*)(ob + w * C_ + o4) = v;
        }
    } else {
        // direct [o][w] stores, float2 per fragment pair
        #pragma unroll
        for (int mi = 0; mi < 4; mi++) {
            int o1 = o0 + m0 + mi*16 + (lane >> 2);
            float bv1 = __ldg(&bias[o1]);
            float bv2 = __ldg(&bias[o1 + 8]);
            float* r1 = out + ((size_t)bh * C_ + o1) * W_;
            float* r2 = r1 + 8 * W_;
            #pragma unroll
            for (int ni = 0; ni < 4; ni++) {
                int wc = n0 + ni*8 + (lane & 3)*2;
                *(float2*)(r1 + wc) = make_float2(d[mi][ni][0] + bv1, d[mi][ni][1] + bv1);
                *(float2*)(r2 + wc) = make_float2(d[mi][ni][2] + bv2, d[mi][ni][3] + bv2);
            }
        }
    }
}

// ---------------------------------------------------------------------------
// Attention (R6, unchanged): 512-thread CTA per (b, h, 128-row q tile),
// online softmax, cp.async double-buffered K/V, FFMA2.
// ---------------------------------------------------------------------------
#define AQP 132
#define AKP 132
#define ASP 132
#define ATT_SMEM ((128*AQP + 2*64*AKP + 128*ASP + 3*128) * 4)

__global__ __launch_bounds__(512, 1) void attn_kernel(
    const float* __restrict__ q, const float* __restrict__ k,
    const float* __restrict__ v, float* __restrict__ out)
{
    extern __shared__ float sm[];
    float* Qt     = sm;
    float* KV0    = sm + 128*AQP;
    float* KV1    = KV0 + 64*AKP;
    float* S      = KV1 + 64*AKP;
    float* m_s    = S + 128*ASP;
    float* corr_s = m_s + 128;
    float* linv_s = corr_s + 128;

    const int q0 = blockIdx.x * 128;
    const int h = blockIdx.y, b = blockIdx.z;
    const int tid = threadIdx.x;
    const int tx = tid & 31, ty = tid >> 5;
    const float scale = 0.17677669529663687f;

    const int bh = b * H_ + h;
    const float* qb = q + bh * (W_ * C_);
    const float* kb = k + bh * (W_ * C_);
    const float* vb = v + bh * (C_ * W_);

    for (int idx = tid; idx < 128*32; idx += 512) {
        int w = idx >> 5, c4 = idx & 31;
        *(float4*)&Qt[w*AQP + c4*4] = *(const float4*)(qb + w*C_ + q0 + c4*4);
    }

    #define LOAD_K(dst, woff, doff) do { \
        for (int idx = tid; idx < 64*32; idx += 512) { \
            int wl = idx >> 5, d4 = idx & 31; \
            cp16(saddr(&(dst)[wl*AKP + d4*4]), kb + ((woff)+wl)*C_ + (doff) + d4*4); \
        } } while (0)
    #define LOAD_V(dst, coff) do { \
        for (int idx = tid; idx < 64*32; idx += 512) { \
            int dl = idx >> 5, w4 = idx & 31; \
            cp16(saddr(&(dst)[dl*AKP + w4*4]), vb + ((coff)+dl)*W_ + w4*4); \
        } } while (0)

    ull oacc2[8][2];
    #pragma unroll
    for (int i = 0; i < 8; i++) { oacc2[i][0]=0ULL; oacc2[i][1]=0ULL; }

    LOAD_K(KV0, 0, 0); CP_COMMIT; CP_WAIT0; __syncthreads();

    for (int dt = 0; dt < 2; dt++) {
        ull sacc2[4][4];
        #pragma unroll
        for (int p = 0; p < 4; p++) { sacc2[p][0]=0ULL; sacc2[p][1]=0ULL; sacc2[p][2]=0ULL; sacc2[p][3]=0ULL; }

        LOAD_K(KV1, 64, dt*128); CP_COMMIT;
        #pragma unroll 2
        for (int wl = 0; wl < 64; wl++) {
            const ull* qp = (const ull*)&Qt[wl*AQP + ty*8];
            float4 kf = *(const float4*)&KV0[wl*AKP + tx*4];
            ull b0 = pack2(kf.x), b1 = pack2(kf.y), b2 = pack2(kf.z), b3 = pack2(kf.w);
            #pragma unroll
            for (int p = 0; p < 4; p++) {
                ull a = qp[p];
                ffma2(sacc2[p][0], a, b0);
                ffma2(sacc2[p][1], a, b1);
                ffma2(sacc2[p][2], a, b2);
                ffma2(sacc2[p][3], a, b3);
            }
        }
        CP_WAIT0; __syncthreads();

        LOAD_V(KV0, dt*128); CP_COMMIT;
        #pragma unroll 2
        for (int wl = 0; wl < 64; wl++) {
            const ull* qp = (const ull*)&Qt[(64+wl)*AQP + ty*8];
            float4 kf = *(const float4*)&KV1[wl*AKP + tx*4];
            ull b0 = pack2(kf.x), b1 = pack2(kf.y), b2 = pack2(kf.z), b3 = pack2(kf.w);
            #pragma unroll
            for (int p = 0; p < 4; p++) {
                ull a = qp[p];
                ffma2(sacc2[p][0], a, b0);
                ffma2(sacc2[p][1], a, b1);
                ffma2(sacc2[p][2], a, b2);
                ffma2(sacc2[p][3], a, b3);
            }
        }
        {
            ull sc2 = pack2(scale);
            #pragma unroll
            for (int p = 0; p < 4; p++) {
                float2 f0 = unpack2(mul2(sacc2[p][0], sc2));
                float2 f1 = unpack2(mul2(sacc2[p][1], sc2));
                float2 f2 = unpack2(mul2(sacc2[p][2], sc2));
                float2 f3 = unpack2(mul2(sacc2[p][3], sc2));
                int r0 = ty*8 + 2*p;
                *(float4*)&S[r0*ASP + tx*4]     = make_float4(f0.x, f1.x, f2.x, f3.x);
                *(float4*)&S[(r0+1)*ASP + tx*4] = make_float4(f0.y, f1.y, f2.y, f3.y);
            }
        }
        CP_WAIT0; __syncthreads();

        LOAD_V(KV1, dt*128 + 64); CP_COMMIT;
        {
            int r = tid >> 2, qq = tid & 3;
            float* srow = S + r*ASP + qq*32;
            float mc = -1e30f;
            #pragma unroll 8
            for (int j = 0; j < 32; j++) mc = fmaxf(mc, srow[j]);
            mc = fmaxf(mc, __shfl_xor_sync(0xffffffffu, mc, 1));
            mc = fmaxf(mc, __shfl_xor_sync(0xffffffffu, mc, 2));
            float m_old = (dt == 0) ? -1e30f : m_s[r];
            float m_new = fmaxf(m_old, mc);
            float l = 0.f;
            #pragma unroll 8
            for (int j = 0; j < 32; j++) { float e = __expf(srow[j] - m_new); srow[j] = e; l += e; }
            l += __shfl_xor_sync(0xffffffffu, l, 1);
            l += __shfl_xor_sync(0xffffffffu, l, 2);
            if (qq == 0) {
                if (dt == 0) { m_s[r] = m_new; linv_s[r] = l; corr_s[r] = 1.f; }
                else {
                    float corr = __expf(m_old - m_new);
                    m_s[r] = m_new;
                    corr_s[r] = corr;
                    linv_s[r] = 1.f / (linv_s[r] * corr + l);
                }
            }
        }
        CP_WAIT0; __syncthreads();

        if (dt == 1) {
            #pragma unroll
            for (int i = 0; i < 8; i++) {
                ull c2 = pack2(corr_s[ty*8 + i]);
                oacc2[i][0] = mul2(oacc2[i][0], c2);
                oacc2[i][1] = mul2(oacc2[i][1], c2);
            }
        }

        for (int d4 = 0; d4 < 64; d4 += 4) {
            float4 pf[8];
            #pragma unroll
            for (int i = 0; i < 8; i++)
                pf[i] = *(const float4*)&S[(ty*8 + i)*ASP + d4];
            #pragma unroll
            for (int dd = 0; dd < 4; dd++) {
                const ull* vp = (const ull*)&KV0[(d4+dd)*AKP + tx*4];
                ull v0 = vp[0], v1 = vp[1];
                #pragma unroll
                for (int i = 0; i < 8; i++) {
                    float p = (dd==0) ? pf[i].x : (dd==1) ? pf[i].y : (dd==2) ? pf[i].z : pf[i].w;
                    ull p2 = pack2(p);
                    ffma2(oacc2[i][0], p2, v0);
                    ffma2(oacc2[i][1], p2, v1);
                }
            }
        }
        __syncthreads();

        if (dt == 0) { LOAD_K(KV0, 0, 128); CP_COMMIT; }
        for (int d4 = 0; d4 < 64; d4 += 4) {
            float4 pf[8];
            #pragma unroll
            for (int i = 0; i < 8; i++)
                pf[i] = *(const float4*)&S[(ty*8 + i)*ASP + 64 + d4];
            #pragma unroll
            for (int dd = 0; dd < 4; dd++) {
                const ull* vp = (const ull*)&KV1[(d4+dd)*AKP + tx*4];
                ull v0 = vp[0], v1 = vp[1];
                #pragma unroll
                for (int i = 0; i < 8; i++) {
                    float p = (dd==0) ? pf[i].x : (dd==1) ? pf[i].y : (dd==2) ? pf[i].z : pf[i].w;
                    ull p2 = pack2(p);
                    ffma2(oacc2[i][0], p2, v0);
                    ffma2(oacc2[i][1], p2, v1);
                }
            }
        }
        if (dt == 0) { CP_WAIT0; __syncthreads(); }
    }
    #undef LOAD_K
    #undef LOAD_V

    #pragma unroll
    for (int i = 0; i < 8; i++) {
        float inv = linv_s[ty*8 + i];
        int cc = q0 + ty*8 + i;
        float2 o0 = unpack2(oacc2[i][0]);
        float2 o1 = unpack2(oacc2[i][1]);
        float4 v4 = make_float4(o0.x*inv, o0.y*inv, o1.x*inv, o1.y*inv);
        *(float4*)(out + ((b*C_ + cc)*H_ + h)*W_ + tx*4) = v4;
    }
}

// ---------------------------------------------------------------------------
extern "C" void kernel_launch(void* const* d_in, const int* in_sizes, int n_in,
                              void* d_out, int out_size)
{
    (void)in_sizes; (void)n_in; (void)out_size;
    const float* hidden = (const float*)d_in[0];
    const float* ctx    = (const float*)d_in[1];
    const float* qdw = (const float*)d_in[2];
    const float* qdb = (const float*)d_in[3];
    const float* qpw = (const float*)d_in[4];
    const float* qpb = (const float*)d_in[5];
    const float* kdw = (const float*)d_in[6];
    const float* kdb = (const float*)d_in[7];
    const float* kpw = (const float*)d_in[8];
    const float* kpb = (const float*)d_in[9];
    const float* vdw = (const float*)d_in[10];
    const float* vdb = (const float*)d_in[11];
    const float* vpw = (const float*)d_in[12];
    const float* vpb = (const float*)d_in[13];
    float* out = (float*)d_out;

    float *tmp, *qp, *kp, *vp;
    __nv_bfloat16 *whi, *wlo, *thi, *tlo;
    cudaGetSymbolAddress((void**)&tmp, g_tmp);
    cudaGetSymbolAddress((void**)&qp,  g_q);
    cudaGetSymbolAddress((void**)&kp,  g_k);
    cudaGetSymbolAddress((void**)&vp,  g_v);
    cudaGetSymbolAddress((void**)&whi, g_whi);
    cudaGetSymbolAddress((void**)&wlo, g_wlo);
    cudaGetSymbolAddress((void**)&thi, g_thi);
    cudaGetSymbolAddress((void**)&tlo, g_tlo);

    cudaFuncSetAttribute(attn_kernel, cudaFuncAttributeMaxDynamicSharedMemorySize, ATT_SMEM);
    cudaFuncSetAttribute(pw_mma_kernel<1>, cudaFuncAttributeMaxDynamicSharedMemorySize, PWS_SMEM);
    cudaFuncSetAttribute(pw_mma_kernel<0>, cudaFuncAttributeMaxDynamicSharedMemorySize, PWS_SMEM);

    dim3 dwg(H_/4, C_, B_);
    dim3 dwb(32, 4);
    dim3 asg(W_/32, C_/32, B_*H_);
    dim3 asb(32, 8);
    dim3 pwg(2, H_, B_);
    dim3 atg(2, H_, B_);

    // weight splits (bf16 hi/lo, K-major)
    wsplit_kernel<<<C_*C_/256, 256>>>(qpw, whi,            wlo);
    wsplit_kernel<<<C_*C_/256, 256>>>(kpw, whi + C_*C_,    wlo + C_*C_);
    wsplit_kernel<<<C_*C_/256, 256>>>(vpw, whi + 2*C_*C_,  wlo + 2*C_*C_);

    // q
    dw_kernel<<<dwg, dwb>>>(hidden, qdw, qdb, tmp);
    asplit_kernel<<<asg, asb>>>(tmp, thi, tlo);
    pw_mma_kernel<1><<<pwg, 256, PWS_SMEM>>>(thi, tlo, whi, wlo, qpb, qp);
    // k
    dw_kernel<<<dwg, dwb>>>(ctx, kdw, kdb, tmp);
    asplit_kernel<<<asg, asb>>>(tmp, thi, tlo);
    pw_mma_kernel<1><<<pwg, 256, PWS_SMEM>>>(thi, tlo, whi + C_*C_, wlo + C_*C_, kpb, kp);
    // v
    dw_kernel<<<dwg, dwb>>>(ctx, vdw, vdb, tmp);
    asplit_kernel<<<asg, asb>>>(tmp, thi, tlo);
    pw_mma_kernel<0><<<pwg, 256, PWS_SMEM>>>(thi, tlo, whi + 2*C_*C_, wlo + 2*C_*C_, vpb, vp);

    attn_kernel<<<atg, 512, ATT_SMEM>>>(qp, kp, vp, out);
}

// round 9
// speedup vs baseline: 3.3843x; 1.4041x over previous
#include <cuda_runtime.h>
#include <cuda_bf16.h>
#include <cstdint>

#define B_ 8
#define C_ 256
#define H_ 128
#define W_ 128
#define NEL (B_*C_*H_*W_)

// Scratch (no allocation allowed -> __device__ globals)
__device__ float g_tmp[NEL];
__device__ __nv_bfloat16 g_whi[3 * C_ * C_];   // weight hi, K-major [o][c]
__device__ __nv_bfloat16 g_wlo[3 * C_ * C_];   // weight lo
__device__ __nv_bfloat16 g_thi[NEL];           // activation hi, [b][h][w][c]
__device__ __nv_bfloat16 g_tlo[NEL];           // activation lo
__device__ __nv_bfloat16 g_qhi[NEL];           // q hi, [b][h][c][w]
__device__ __nv_bfloat16 g_qlo[NEL];
__device__ __nv_bfloat16 g_khi[NEL];           // k hi, [b][h][c][w]
__device__ __nv_bfloat16 g_klo[NEL];
__device__ __nv_bfloat16 g_vhi[NEL];           // v hi, [b][h][w][c]
__device__ __nv_bfloat16 g_vlo[NEL];

// ---- cp.async helpers ----
__device__ __forceinline__ uint32_t saddr(const void* p) {
    return (uint32_t)__cvta_generic_to_shared(p);
}
__device__ __forceinline__ void cp16(uint32_t dst, const void* src) {
    asm volatile("cp.async.cg.shared.global [%0], [%1], 16;" :: "r"(dst), "l"(src));
}
#define CP_COMMIT asm volatile("cp.async.commit_group;")
#define CP_WAIT0  asm volatile("cp.async.wait_group 0;")

// ---- mma.sync / ldmatrix helpers (plain sm_103 features) ----
__device__ __forceinline__ void ldmx4(uint32_t* r, uint32_t addr) {
    asm volatile("ldmatrix.sync.aligned.m8n8.x4.shared.b16 {%0,%1,%2,%3}, [%4];"
                 : "=r"(r[0]), "=r"(r[1]), "=r"(r[2]), "=r"(r[3]) : "r"(addr));
}
__device__ __forceinline__ void mma16816(float* d, const uint32_t* a, const uint32_t* b) {
    asm volatile(
        "mma.sync.aligned.m16n8k16.row.col.f32.bf16.bf16.f32 "
        "{%0,%1,%2,%3}, {%4,%5,%6,%7}, {%8,%9}, {%0,%1,%2,%3};"
        : "+f"(d[0]), "+f"(d[1]), "+f"(d[2]), "+f"(d[3])
        : "r"(a[0]), "r"(a[1]), "r"(a[2]), "r"(a[3]), "r"(b[0]), "r"(b[1]));
}
__device__ __forceinline__ void split_bf16(float x, __nv_bfloat16& h, __nv_bfloat16& l) {
    h = __float2bfloat16_rn(x);
    l = __float2bfloat16_rn(x - __bfloat162float(h));
}

// ---------------------------------------------------------------------------
// Weight split: W[o][c] fp32 -> hi/lo bf16 (K-major, layout unchanged)
// ---------------------------------------------------------------------------
__global__ void wsplit_kernel(const float* __restrict__ W,
                              __nv_bfloat16* __restrict__ hi,
                              __nv_bfloat16* __restrict__ lo)
{
    int i = blockIdx.x * 256 + threadIdx.x;
    split_bf16(W[i], hi[i], lo[i]);
}

// ---------------------------------------------------------------------------
// Activation split + transpose: t[b][c][h][w] fp32 -> hi/lo [b][h][w][c] bf16
// grid (W/32, C/32, B*H), block (32,8)
// ---------------------------------------------------------------------------
__global__ void asplit_kernel(const float* __restrict__ t,
                              __nv_bfloat16* __restrict__ hi,
                              __nv_bfloat16* __restrict__ lo)
{
    __shared__ float tile[32][33];
    const int bz = blockIdx.z;           // b*H + h
    const int b = bz >> 7, h = bz & 127;
    const int w0 = blockIdx.x * 32, c0 = blockIdx.y * 32;
    const int tx = threadIdx.x, ty = threadIdx.y;
    #pragma unroll
    for (int j = 0; j < 32; j += 8)
        tile[ty + j][tx] = t[((b * C_ + c0 + ty + j) * H_ + h) * W_ + w0 + tx];
    __syncthreads();
    #pragma unroll
    for (int j = 0; j < 32; j += 8) {
        int idx = (bz * W_ + w0 + ty + j) * C_ + c0 + tx;
        split_bf16(tile[tx][ty + j], hi[idx], lo[idx]);
    }
}

// ---------------------------------------------------------------------------
// Depthwise 3x3 (SAME) + bias, 4 outputs/thread.  grid (H/4, C, B), block (32,4)
// ---------------------------------------------------------------------------
__global__ __launch_bounds__(128) void dw_kernel(
    const float* __restrict__ x, const float* __restrict__ wgt,
    const float* __restrict__ bias, float* __restrict__ out)
{
    const int c = blockIdx.y, b = blockIdx.z;
    const int h = blockIdx.x * 4 + threadIdx.y;
    const int w0 = threadIdx.x * 4;
    const float* wc = wgt + c * 9;
    const float* plane = x + (b * C_ + c) * (H_ * W_);
    float bv = __ldg(&bias[c]);
    float4 acc = make_float4(bv, bv, bv, bv);
    #pragma unroll
    for (int i = 0; i < 3; i++) {
        int hh = h + i - 1;
        if (hh < 0 || hh >= H_) continue;
        const float* row = plane + hh * W_;
        float4 xc = *(const float4*)(row + w0);
        float xl = (w0 > 0)        ? __ldg(&row[w0 - 1]) : 0.f;
        float xr = (w0 + 4 < W_)   ? __ldg(&row[w0 + 4]) : 0.f;
        float wl = __ldg(&wc[i*3+0]), wm = __ldg(&wc[i*3+1]), wr = __ldg(&wc[i*3+2]);
        acc.x += wl*xl   + wm*xc.x + wr*xc.y;
        acc.y += wl*xc.x + wm*xc.y + wr*xc.z;
        acc.z += wl*xc.y + wm*xc.z + wr*xc.w;
        acc.w += wl*xc.z + wm*xc.w + wr*xr;
    }
    *(float4*)(out + (b * C_ + c) * (H_*W_) + h * W_ + w0) = acc;
}

// ---------------------------------------------------------------------------
// Pointwise 1x1 split-bf16 mma.sync GEMM, emitting bf16 hi/lo outputs.
// TRANS=0: out [b][h][o][w] (q,k — direct stores)
// TRANS=1: out [b][h][w][o] (v — smem bounce)
// ---------------------------------------------------------------------------
#define MP 136
#define PW_AHI 0
#define PW_ALO (128*MP)
#define PW_BHI (2*128*MP)
#define PW_BLO (3*128*MP)
#define PWS_SMEM (4*128*MP*2)

template<int TRANS>
__global__ __launch_bounds__(256, 1) void pw_mma_kernel(
    const __nv_bfloat16* __restrict__ thi, const __nv_bfloat16* __restrict__ tlo,
    const __nv_bfloat16* __restrict__ whi, const __nv_bfloat16* __restrict__ wlo,
    const float* __restrict__ bias,
    __nv_bfloat16* __restrict__ ohi, __nv_bfloat16* __restrict__ olo)
{
    extern __shared__ char psm[];
    const uint32_t sbase = saddr(psm);
    const int o0 = blockIdx.x * 128;
    const int h = blockIdx.y, b = blockIdx.z;
    const int bh = b * H_ + h;
    const int tid = threadIdx.x;
    const int wid = tid >> 5, lane = tid & 31;
    const int m0 = (wid >> 2) * 64;
    const int n0 = (wid & 3) * 32;

    float d[4][4][4];
    #pragma unroll
    for (int mi = 0; mi < 4; mi++)
        #pragma unroll
        for (int ni = 0; ni < 4; ni++)
            { d[mi][ni][0]=0.f; d[mi][ni][1]=0.f; d[mi][ni][2]=0.f; d[mi][ni][3]=0.f; }

    int a_off[4], b_off[2];
    #pragma unroll
    for (int mi = 0; mi < 4; mi++)
        a_off[mi] = (m0 + mi*16 + (lane & 15)) * MP + (lane >> 4) * 8;
    #pragma unroll
    for (int p = 0; p < 2; p++) {
        int tl = lane >> 3;
        b_off[p] = (n0 + p*16 + (tl >> 1)*8 + (lane & 7)) * MP + (tl & 1) * 8;
    }

    const __nv_bfloat16* tbh = thi + (size_t)bh * (W_ * C_);
    const __nv_bfloat16* tbl = tlo + (size_t)bh * (W_ * C_);
    const int rl = tid >> 4, c8 = (tid & 15) * 8;

    for (int ch = 0; ch < 2; ch++) {
        const int kk = ch * 128;
        __syncthreads();
        #pragma unroll
        for (int rr = 0; rr < 8; rr++) {
            int r = rl + rr * 16;
            uint32_t doff = (uint32_t)(r * MP + c8) * 2;
            cp16(sbase + PW_AHI*2 + doff, whi + (o0 + r) * C_ + kk + c8);
            cp16(sbase + PW_ALO*2 + doff, wlo + (o0 + r) * C_ + kk + c8);
            cp16(sbase + PW_BHI*2 + doff, tbh + r * C_ + kk + c8);
            cp16(sbase + PW_BLO*2 + doff, tbl + r * C_ + kk + c8);
        }
        CP_COMMIT; CP_WAIT0; __syncthreads();

        #pragma unroll
        for (int ks = 0; ks < 8; ks++) {
            const int k0 = ks * 16;
            uint32_t ah[4][4], al[4][4], bh2[2][4], bl2[2][4];
            #pragma unroll
            for (int mi = 0; mi < 4; mi++) {
                ldmx4(ah[mi], sbase + (PW_AHI + a_off[mi] + k0) * 2);
                ldmx4(al[mi], sbase + (PW_ALO + a_off[mi] + k0) * 2);
            }
            #pragma unroll
            for (int p = 0; p < 2; p++) {
                ldmx4(bh2[p], sbase + (PW_BHI + b_off[p] + k0) * 2);
                ldmx4(bl2[p], sbase + (PW_BLO + b_off[p] + k0) * 2);
            }
            // product-outer ordering: 16 independent accumulators between reuse
            #pragma unroll
            for (int mi = 0; mi < 4; mi++)
                #pragma unroll
                for (int ni = 0; ni < 4; ni++)
                    mma16816(d[mi][ni], ah[mi], &bh2[ni >> 1][(ni & 1) * 2]);
            #pragma unroll
            for (int mi = 0; mi < 4; mi++)
                #pragma unroll
                for (int ni = 0; ni < 4; ni++)
                    mma16816(d[mi][ni], ah[mi], &bl2[ni >> 1][(ni & 1) * 2]);
            #pragma unroll
            for (int mi = 0; mi < 4; mi++)
                #pragma unroll
                for (int ni = 0; ni < 4; ni++)
                    mma16816(d[mi][ni], al[mi], &bh2[ni >> 1][(ni & 1) * 2]);
        }
    }

    if (!TRANS) {
        // direct [o][w] hi/lo stores
        #pragma unroll
        for (int mi = 0; mi < 4; mi++) {
            int o1 = o0 + m0 + mi*16 + (lane >> 2);
            float bv1 = __ldg(&bias[o1]);
            float bv2 = __ldg(&bias[o1 + 8]);
            size_t r1 = ((size_t)bh * C_ + o1) * W_;
            size_t r2 = r1 + 8 * W_;
            #pragma unroll
            for (int ni = 0; ni < 4; ni++) {
                int wc = n0 + ni*8 + (lane & 3)*2;
                __nv_bfloat162 hp, lp;
                split_bf16(d[mi][ni][0] + bv1, hp.x, lp.x);
                split_bf16(d[mi][ni][1] + bv1, hp.y, lp.y);
                *(__nv_bfloat162*)(ohi + r1 + wc) = hp;
                *(__nv_bfloat162*)(olo + r1 + wc) = lp;
                split_bf16(d[mi][ni][2] + bv2, hp.x, lp.x);
                split_bf16(d[mi][ni][3] + bv2, hp.y, lp.y);
                *(__nv_bfloat162*)(ohi + r2 + wc) = hp;
                *(__nv_bfloat162*)(olo + r2 + wc) = lp;
            }
        }
    } else {
        // bounce through smem to [w][o] layout
        __syncthreads();
        float* DS = (float*)psm;
        #pragma unroll
        for (int mi = 0; mi < 4; mi++) {
            int m_ = m0 + mi*16 + (lane >> 2);
            #pragma unroll
            for (int ni = 0; ni < 4; ni++) {
                int n_ = n0 + ni*8 + (lane & 3)*2;
                DS[n_*132 + m_]         = d[mi][ni][0];
                DS[(n_+1)*132 + m_]     = d[mi][ni][1];
                DS[n_*132 + m_ + 8]     = d[mi][ni][2];
                DS[(n_+1)*132 + m_ + 8] = d[mi][ni][3];
            }
        }
        __syncthreads();
        for (int i = tid; i < 128*32; i += 256) {
            int w = i >> 5, o4 = (i & 31) * 4;
            float4 v = *(float4*)&DS[w*132 + o4];
            float4 bv = *(const float4*)&bias[o0 + o4];
            size_t idx = ((size_t)bh * W_ + w) * C_ + o0 + o4;
            __nv_bfloat162 h01, h23, l01, l23;
            split_bf16(v.x + bv.x, h01.x, l01.x);
            split_bf16(v.y + bv.y, h01.y, l01.y);
            split_bf16(v.z + bv.z, h23.x, l23.x);
            split_bf16(v.w + bv.w, h23.y, l23.y);
            *(__nv_bfloat162*)(ohi + idx)     = h01;
            *(__nv_bfloat162*)(ohi + idx + 2) = h23;
            *(__nv_bfloat162*)(olo + idx)     = l01;
            *(__nv_bfloat162*)(olo + idx + 2) = l23;
        }
    }
}

// ---------------------------------------------------------------------------
// Attention via split-bf16 mma.sync.  One CTA (256 thr, 8 warps) per
// (b, h, 128-row q tile).  Warp = 16 rows x full 128-col chunk, so softmax
// stats live in registers (quad shuffles only).  Online softmax over two
// 128-wide d chunks.  K->V->K streamed through one hi/lo smem buffer; P is
// re-split to bf16 hi/lo in smem for the PV mma.  O accumulated in regs.
// ---------------------------------------------------------------------------
#define AMP 136
#define AQHI 0
#define AQLO (128*AMP)
#define AKVHI (2*128*AMP)
#define AKVLO (3*128*AMP)
#define APHI (4*128*AMP)
#define APLO (5*128*AMP)
#define ATT_SMEM (6*128*AMP*2)   // 208896 bytes

__global__ __launch_bounds__(256, 1) void attn_mma_kernel(
    const __nv_bfloat16* __restrict__ qhi, const __nv_bfloat16* __restrict__ qlo,
    const __nv_bfloat16* __restrict__ khi, const __nv_bfloat16* __restrict__ klo,
    const __nv_bfloat16* __restrict__ vhi, const __nv_bfloat16* __restrict__ vlo,
    float* __restrict__ out)
{
    extern __shared__ char smraw[];
    const uint32_t sb = saddr(smraw);
    const int r0 = blockIdx.x * 128;
    const int h = blockIdx.y, b = blockIdx.z;
    const int bh = b * H_ + h;
    const size_t bho = (size_t)bh * (C_ * W_);
    const int tid = threadIdx.x;
    const int wid = tid >> 5, lane = tid & 31;
    const int m0 = wid * 16;
    const float scale = 0.17677669529663687f;   // 1/sqrt(32)

    const int a_off = (m0 + (lane & 15)) * AMP + (lane >> 4) * 8;
    int b_off[8];
    {
        int tl = lane >> 3;
        #pragma unroll
        for (int p = 0; p < 8; p++)
            b_off[p] = (p*16 + (tl >> 1)*8 + (lane & 7)) * AMP + (tl & 1) * 8;
    }
    const int ra = m0 + (lane >> 2);     // row a (within tile)
    const int rb = ra + 8;               // row b
    const int pcol0 = (lane & 3) * 2;

    const int rl = tid >> 4, c8 = (tid & 15) * 8;
    // stage a 128x128 bf16 tile (src row length rlen, row offset roff, col offset coff)
    #define ALOAD(dstbase, src, rlen, roff, coff) do { \
        _Pragma("unroll") \
        for (int j = 0; j < 8; j++) { \
            int r = rl + j * 16; \
            cp16(sb + ((dstbase) + r * AMP + c8) * 2, \
                 (src) + ((size_t)((roff) + r)) * (rlen) + (coff) + c8); \
        } } while (0)

    float o[16][4];
    #pragma unroll
    for (int nt = 0; nt < 16; nt++) { o[nt][0]=0.f; o[nt][1]=0.f; o[nt][2]=0.f; o[nt][3]=0.f; }
    float m_a = -1e30f, m_b = -1e30f, l_a = 0.f, l_b = 0.f;

    // Q (persistent) + K chunk 0
    ALOAD(AQHI,  qhi + bho, W_, r0, 0);
    ALOAD(AQLO,  qlo + bho, W_, r0, 0);
    ALOAD(AKVHI, khi + bho, W_, 0, 0);
    ALOAD(AKVLO, klo + bho, W_, 0, 0);
    CP_COMMIT; CP_WAIT0; __syncthreads();

    for (int dt = 0; dt < 2; dt++) {
        // ---- S = Q K^T chunk (3 split products) ----
        float s[16][4];
        #pragma unroll
        for (int nt = 0; nt < 16; nt++) { s[nt][0]=0.f; s[nt][1]=0.f; s[nt][2]=0.f; s[nt][3]=0.f; }
        #pragma unroll
        for (int kw = 0; kw < 8; kw++) {
            uint32_t qh[4], ql[4];
            ldmx4(qh, sb + (AQHI + a_off + kw*16) * 2);
            ldmx4(ql, sb + (AQLO + a_off + kw*16) * 2);
            #pragma unroll
            for (int hf = 0; hf < 2; hf++) {
                uint32_t bh4[4][4], bl4[4][4];
                #pragma unroll
                for (int p = 0; p < 4; p++) {
                    ldmx4(bh4[p], sb + (AKVHI + b_off[hf*4+p] + kw*16) * 2);
                    ldmx4(bl4[p], sb + (AKVLO + b_off[hf*4+p] + kw*16) * 2);
                }
                #pragma unroll
                for (int p8 = 0; p8 < 8; p8++)
                    mma16816(s[hf*8+p8], qh, &bh4[p8 >> 1][(p8 & 1)*2]);
                #pragma unroll
                for (int p8 = 0; p8 < 8; p8++)
                    mma16816(s[hf*8+p8], qh, &bl4[p8 >> 1][(p8 & 1)*2]);
                #pragma unroll
                for (int p8 = 0; p8 < 8; p8++)
                    mma16816(s[hf*8+p8], ql, &bh4[p8 >> 1][(p8 & 1)*2]);
            }
        }
        __syncthreads();                      // K buffer fully consumed
        // prefetch V chunk (overlaps softmax)
        ALOAD(AKVHI, vhi + bho, C_, 0, dt*128);
        ALOAD(AKVLO, vlo + bho, C_, 0, dt*128);
        CP_COMMIT;

        // ---- online softmax in registers ----
        #pragma unroll
        for (int nt = 0; nt < 16; nt++) {
            s[nt][0] *= scale; s[nt][1] *= scale; s[nt][2] *= scale; s[nt][3] *= scale;
        }
        float mc_a = -1e30f, mc_b = -1e30f;
        #pragma unroll
        for (int nt = 0; nt < 16; nt++) {
            mc_a = fmaxf(mc_a, fmaxf(s[nt][0], s[nt][1]));
            mc_b = fmaxf(mc_b, fmaxf(s[nt][2], s[nt][3]));
        }
        mc_a = fmaxf(mc_a, __shfl_xor_sync(0xffffffffu, mc_a, 1));
        mc_a = fmaxf(mc_a, __shfl_xor_sync(0xffffffffu, mc_a, 2));
        mc_b = fmaxf(mc_b, __shfl_xor_sync(0xffffffffu, mc_b, 1));
        mc_b = fmaxf(mc_b, __shfl_xor_sync(0xffffffffu, mc_b, 2));
        float m_na = fmaxf(m_a, mc_a), m_nb = fmaxf(m_b, mc_b);
        float ca = __expf(m_a - m_na), cb = __expf(m_b - m_nb);
        float la_c = 0.f, lb_c = 0.f;
        #pragma unroll
        for (int nt = 0; nt < 16; nt++) {
            float e0 = __expf(s[nt][0] - m_na), e1 = __expf(s[nt][1] - m_na);
            float e2 = __expf(s[nt][2] - m_nb), e3 = __expf(s[nt][3] - m_nb);
            la_c += e0 + e1; lb_c += e2 + e3;
            int col = nt*8 + pcol0;
            __nv_bfloat162 hp, lp;
            split_bf16(e0, hp.x, lp.x); split_bf16(e1, hp.y, lp.y);
            *(__nv_bfloat162*)(smraw + (APHI + ra*AMP + col)*2) = hp;
            *(__nv_bfloat162*)(smraw + (APLO + ra*AMP + col)*2) = lp;
            split_bf16(e2, hp.x, lp.x); split_bf16(e3, hp.y, lp.y);
            *(__nv_bfloat162*)(smraw + (APHI + rb*AMP + col)*2) = hp;
            *(__nv_bfloat162*)(smraw + (APLO + rb*AMP + col)*2) = lp;
            o[nt][0] *= ca; o[nt][1] *= ca; o[nt][2] *= cb; o[nt][3] *= cb;
        }
        la_c += __shfl_xor_sync(0xffffffffu, la_c, 1);
        la_c += __shfl_xor_sync(0xffffffffu, la_c, 2);
        lb_c += __shfl_xor_sync(0xffffffffu, lb_c, 1);
        lb_c += __shfl_xor_sync(0xffffffffu, lb_c, 2);
        l_a = l_a * ca + la_c;  l_b = l_b * cb + lb_c;
        m_a = m_na;  m_b = m_nb;
        __syncwarp();                         // P rows (warp-owned) visible to ldmatrix
        CP_WAIT0; __syncthreads();            // V ready

        // ---- O += P V chunk (3 split products) ----
        #pragma unroll
        for (int kw = 0; kw < 8; kw++) {
            uint32_t ph[4], pl[4];
            ldmx4(ph, sb + (APHI + a_off + kw*16) * 2);
            ldmx4(pl, sb + (APLO + a_off + kw*16) * 2);
            #pragma unroll
            for (int hf = 0; hf < 2; hf++) {
                uint32_t bh4[4][4], bl4[4][4];
                #pragma unroll
                for (int p = 0; p < 4; p++) {
                    ldmx4(bh4[p], sb + (AKVHI + b_off[hf*4+p] + kw*16) * 2);
                    ldmx4(bl4[p], sb + (AKVLO + b_off[hf*4+p] + kw*16) * 2);
                }
                #pragma unroll
                for (int p8 = 0; p8 < 8; p8++)
                    mma16816(o[hf*8+p8], ph, &bh4[p8 >> 1][(p8 & 1)*2]);
                #pragma unroll
                for (int p8 = 0; p8 < 8; p8++)
                    mma16816(o[hf*8+p8], ph, &bl4[p8 >> 1][(p8 & 1)*2]);
                #pragma unroll
                for (int p8 = 0; p8 < 8; p8++)
                    mma16816(o[hf*8+p8], pl, &bh4[p8 >> 1][(p8 & 1)*2]);
            }
        }

        if (dt == 0) {
            __syncthreads();                  // V consumed; reload K chunk 1
            ALOAD(AKVHI, khi + bho, W_, 128, 0);
            ALOAD(AKVLO, klo + bho, W_, 128, 0);
            CP_COMMIT; CP_WAIT0; __syncthreads();
        }
    }
    #undef ALOAD

    // ---- epilogue: normalize, bounce via smem, coalesced stores ----
    float inva = 1.f / l_a, invb = 1.f / l_b;
    __syncthreads();                          // all PV reads of P region done
    float* OS = (float*)(smraw + (size_t)APHI * 2);
    #pragma unroll
    for (int nt = 0; nt < 16; nt++) {
        int col = nt*8 + pcol0;
        *(float2*)&OS[ra*132 + col] = make_float2(o[nt][0]*inva, o[nt][1]*inva);
        *(float2*)&OS[rb*132 + col] = make_float2(o[nt][2]*invb, o[nt][3]*invb);
    }
    __syncthreads();
    for (int i = tid; i < 128*32; i += 256) {
        int r = i >> 5, w4 = (i & 31) * 4;
        *(float4*)(out + ((size_t)(b*C_ + r0 + r)*H_ + h)*W_ + w4) = *(float4*)&OS[r*132 + w4];
    }
}

// ---------------------------------------------------------------------------
extern "C" void kernel_launch(void* const* d_in, const int* in_sizes, int n_in,
                              void* d_out, int out_size)
{
    (void)in_sizes; (void)n_in; (void)out_size;
    const float* hidden = (const float*)d_in[0];
    const float* ctx    = (const float*)d_in[1];
    const float* qdw = (const float*)d_in[2];
    const float* qdb = (const float*)d_in[3];
    const float* qpw = (const float*)d_in[4];
    const float* qpb = (const float*)d_in[5];
    const float* kdw = (const float*)d_in[6];
    const float* kdb = (const float*)d_in[7];
    const float* kpw = (const float*)d_in[8];
    const float* kpb = (const float*)d_in[9];
    const float* vdw = (const float*)d_in[10];
    const float* vdb = (const float*)d_in[11];
    const float* vpw = (const float*)d_in[12];
    const float* vpb = (const float*)d_in[13];
    float* out = (float*)d_out;

    float* tmp;
    __nv_bfloat16 *whi, *wlo, *thi, *tlo;
    __nv_bfloat16 *qhi, *qlo, *khi, *klo, *vhi, *vlo;
    cudaGetSymbolAddress((void**)&tmp, g_tmp);
    cudaGetSymbolAddress((void**)&whi, g_whi);
    cudaGetSymbolAddress((void**)&wlo, g_wlo);
    cudaGetSymbolAddress((void**)&thi, g_thi);
    cudaGetSymbolAddress((void**)&tlo, g_tlo);
    cudaGetSymbolAddress((void**)&qhi, g_qhi);
    cudaGetSymbolAddress((void**)&qlo, g_qlo);
    cudaGetSymbolAddress((void**)&khi, g_khi);
    cudaGetSymbolAddress((void**)&klo, g_klo);
    cudaGetSymbolAddress((void**)&vhi, g_vhi);
    cudaGetSymbolAddress((void**)&vlo, g_vlo);

    cudaFuncSetAttribute(pw_mma_kernel<0>, cudaFuncAttributeMaxDynamicSharedMemorySize, PWS_SMEM);
    cudaFuncSetAttribute(pw_mma_kernel<1>, cudaFuncAttributeMaxDynamicSharedMemorySize, PWS_SMEM);
    cudaFuncSetAttribute(attn_mma_kernel, cudaFuncAttributeMaxDynamicSharedMemorySize, ATT_SMEM);

    dim3 dwg(H_/4, C_, B_);
    dim3 dwb(32, 4);
    dim3 asg(W_/32, C_/32, B_*H_);
    dim3 asb(32, 8);
    dim3 pwg(2, H_, B_);
    dim3 atg(2, H_, B_);

    wsplit_kernel<<<C_*C_/256, 256>>>(qpw, whi,            wlo);
    wsplit_kernel<<<C_*C_/256, 256>>>(kpw, whi + C_*C_,    wlo + C_*C_);
    wsplit_kernel<<<C_*C_/256, 256>>>(vpw, whi + 2*C_*C_,  wlo + 2*C_*C_);

    // q -> [b][h][c][w] hi/lo
    dw_kernel<<<dwg, dwb>>>(hidden, qdw, qdb, tmp);
    asplit_kernel<<<asg, asb>>>(tmp, thi, tlo);
    pw_mma_kernel<0><<<pwg, 256, PWS_SMEM>>>(thi, tlo, whi, wlo, qpb, qhi, qlo);
    // k -> [b][h][c][w] hi/lo
    dw_kernel<<<dwg, dwb>>>(ctx, kdw, kdb, tmp);
    asplit_kernel<<<asg, asb>>>(tmp, thi, tlo);
    pw_mma_kernel<0><<<pwg, 256, PWS_SMEM>>>(thi, tlo, whi + C_*C_, wlo + C_*C_, kpb, khi, klo);
    // v -> [b][h][w][c] hi/lo
    dw_kernel<<<dwg, dwb>>>(ctx, vdw, vdb, tmp);
    asplit_kernel<<<asg, asb>>>(tmp, thi, tlo);
    pw_mma_kernel<1><<<pwg, 256, PWS_SMEM>>>(thi, tlo, whi + 2*C_*C_, wlo + 2*C_*C_, vpb, vhi, vlo);

    attn_mma_kernel<<<atg, 256, ATT_SMEM>>>(qhi, qlo, khi, klo, vhi, vlo, out);
}

// round 10
// speedup vs baseline: 3.5740x; 1.0561x over previous
#include <cuda_runtime.h>
#include <cuda_bf16.h>
#include <cstdint>

#define B_ 8
#define C_ 256
#define H_ 128
#define W_ 128
#define NEL (B_*C_*H_*W_)

// Scratch (no allocation allowed -> __device__ globals)
__device__ __nv_bfloat16 g_whi[3 * C_ * C_];   // weight hi, K-major [o][c]
__device__ __nv_bfloat16 g_wlo[3 * C_ * C_];   // weight lo
__device__ __nv_bfloat16 g_thi[NEL];           // activation hi, [b][h][w][c]
__device__ __nv_bfloat16 g_tlo[NEL];           // activation lo
__device__ __nv_bfloat16 g_qhi[NEL];           // q hi, [b][h][c][w]
__device__ __nv_bfloat16 g_qlo[NEL];
__device__ __nv_bfloat16 g_khi[NEL];           // k hi, [b][h][c][w]
__device__ __nv_bfloat16 g_klo[NEL];
__device__ __nv_bfloat16 g_vhi[NEL];           // v hi, [b][h][w][c]
__device__ __nv_bfloat16 g_vlo[NEL];

// ---- cp.async helpers ----
__device__ __forceinline__ uint32_t saddr(const void* p) {
    return (uint32_t)__cvta_generic_to_shared(p);
}
__device__ __forceinline__ void cp16(uint32_t dst, const void* src) {
    asm volatile("cp.async.cg.shared.global [%0], [%1], 16;" :: "r"(dst), "l"(src));
}
#define CP_COMMIT asm volatile("cp.async.commit_group;")
#define CP_WAIT0  asm volatile("cp.async.wait_group 0;")
#define CP_WAIT1  asm volatile("cp.async.wait_group 1;")

// ---- mma.sync / ldmatrix helpers (plain sm_103 features) ----
__device__ __forceinline__ void ldmx4(uint32_t* r, uint32_t addr) {
    asm volatile("ldmatrix.sync.aligned.m8n8.x4.shared.b16 {%0,%1,%2,%3}, [%4];"
                 : "=r"(r[0]), "=r"(r[1]), "=r"(r[2]), "=r"(r[3]) : "r"(addr));
}
__device__ __forceinline__ void mma16816(float* d, const uint32_t* a, const uint32_t* b) {
    asm volatile(
        "mma.sync.aligned.m16n8k16.row.col.f32.bf16.bf16.f32 "
        "{%0,%1,%2,%3}, {%4,%5,%6,%7}, {%8,%9}, {%0,%1,%2,%3};"
        : "+f"(d[0]), "+f"(d[1]), "+f"(d[2]), "+f"(d[3])
        : "r"(a[0]), "r"(a[1]), "r"(a[2]), "r"(a[3]), "r"(b[0]), "r"(b[1]));
}
__device__ __forceinline__ void split_bf16(float x, __nv_bfloat16& h, __nv_bfloat16& l) {
    h = __float2bfloat16_rn(x);
    l = __float2bfloat16_rn(x - __bfloat162float(h));
}

// ---------------------------------------------------------------------------
// Weight split: W[o][c] fp32 -> hi/lo bf16 (K-major, layout unchanged)
// ---------------------------------------------------------------------------
__global__ void wsplit_kernel(const float* __restrict__ W,
                              __nv_bfloat16* __restrict__ hi,
                              __nv_bfloat16* __restrict__ lo)
{
    int i = blockIdx.x * 256 + threadIdx.x;
    split_bf16(W[i], hi[i], lo[i]);
}

// ---------------------------------------------------------------------------
// FUSED depthwise 3x3 + bias + transpose + bf16 split:
//   x[b][c][h][w] fp32  ->  hi/lo [b][h][w][c] bf16
// grid (C/32, H, B), block 256.  Phase 1: conv 32c x 128w tile -> smem.
// Phase 2: transposed split-write; each thread stores a contiguous
// 32B hi + 32B lo segment (16 c values) -> full sectors.
// ---------------------------------------------------------------------------
#define DSP 132
__global__ __launch_bounds__(256) void dwsplit_kernel(
    const float* __restrict__ x, const float* __restrict__ wgt,
    const float* __restrict__ bias,
    __nv_bfloat16* __restrict__ hi, __nv_bfloat16* __restrict__ lo)
{
    __shared__ float S[32 * DSP];
    const int c0 = blockIdx.x * 32;
    const int h = blockIdx.y, b = blockIdx.z;
    const int tid = threadIdx.x;
    const int tx = tid & 31, ty = tid >> 5;
    const int w0 = tx * 4;

    #pragma unroll
    for (int j = 0; j < 4; j++) {
        const int cc = ty + j * 8;
        const int c = c0 + cc;
        const float* wc = wgt + c * 9;
        const float* plane = x + (b * C_ + c) * (H_ * W_);
        float bv = __ldg(&bias[c]);
        float4 acc = make_float4(bv, bv, bv, bv);
        #pragma unroll
        for (int i = 0; i < 3; i++) {
            int hh = h + i - 1;
            if (hh < 0 || hh >= H_) continue;
            const float* row = plane + hh * W_;
            float4 xc = *(const float4*)(row + w0);
            float xl = (w0 > 0)      ? __ldg(&row[w0 - 1]) : 0.f;
            float xr = (w0 + 4 < W_) ? __ldg(&row[w0 + 4]) : 0.f;
            float wl = __ldg(&wc[i*3+0]), wm = __ldg(&wc[i*3+1]), wr = __ldg(&wc[i*3+2]);
            acc.x += wl*xl   + wm*xc.x + wr*xc.y;
            acc.y += wl*xc.x + wm*xc.y + wr*xc.z;
            acc.z += wl*xc.y + wm*xc.z + wr*xc.w;
            acc.w += wl*xc.z + wm*xc.w + wr*xr;
        }
        *(float4*)&S[cc * DSP + w0] = acc;
    }
    __syncthreads();

    // Phase 2: thread -> (w = tid&127, 16 consecutive c)
    const int w = tid & 127;
    const int cb = (tid >> 7) * 16;
    __nv_bfloat16 hb[16], lb[16];
    #pragma unroll
    for (int e = 0; e < 16; e++)
        split_bf16(S[(cb + e) * DSP + w], hb[e], lb[e]);
    size_t idx = ((size_t)(b * H_ + h) * W_ + w) * C_ + c0 + cb;
    *(uint4*)(hi + idx)     = *(uint4*)&hb[0];
    *(uint4*)(hi + idx + 8) = *(uint4*)&hb[8];
    *(uint4*)(lo + idx)     = *(uint4*)&lb[0];
    *(uint4*)(lo + idx + 8) = *(uint4*)&lb[8];
}

// ---------------------------------------------------------------------------
// Pointwise 1x1 split-bf16 mma.sync GEMM, double-buffered 64-wide K chunks.
// TRANS=0: out [b][h][o][w] (q,k)   TRANS=1: out [b][h][w][o] (v)
// ---------------------------------------------------------------------------
#define MP2 72
#define PWT (128*MP2)          // elems per tile
#define PW_STG (4*PWT)         // elems per stage (AHI,ALO,BHI,BLO)
#define PWS_SMEM (2*PW_STG*2)  // 147456 bytes

template<int TRANS>
__global__ __launch_bounds__(256, 1) void pw_mma_kernel(
    const __nv_bfloat16* __restrict__ thi, const __nv_bfloat16* __restrict__ tlo,
    const __nv_bfloat16* __restrict__ whi, const __nv_bfloat16* __restrict__ wlo,
    const float* __restrict__ bias,
    __nv_bfloat16* __restrict__ ohi, __nv_bfloat16* __restrict__ olo)
{
    extern __shared__ char psm[];
    const uint32_t sbase = saddr(psm);
    const int o0 = blockIdx.x * 128;
    const int h = blockIdx.y, b = blockIdx.z;
    const int bh = b * H_ + h;
    const int tid = threadIdx.x;
    const int wid = tid >> 5, lane = tid & 31;
    const int m0 = (wid >> 2) * 64;
    const int n0 = (wid & 3) * 32;

    float d[4][4][4];
    #pragma unroll
    for (int mi = 0; mi < 4; mi++)
        #pragma unroll
        for (int ni = 0; ni < 4; ni++)
            { d[mi][ni][0]=0.f; d[mi][ni][1]=0.f; d[mi][ni][2]=0.f; d[mi][ni][3]=0.f; }

    int a_off[4], b_off[2];
    #pragma unroll
    for (int mi = 0; mi < 4; mi++)
        a_off[mi] = (m0 + mi*16 + (lane & 15)) * MP2 + (lane >> 4) * 8;
    #pragma unroll
    for (int p = 0; p < 2; p++) {
        int tl = lane >> 3;
        b_off[p] = (n0 + p*16 + (tl >> 1)*8 + (lane & 7)) * MP2 + (tl & 1) * 8;
    }

    const __nv_bfloat16* tbh = thi + (size_t)bh * (W_ * C_);
    const __nv_bfloat16* tbl = tlo + (size_t)bh * (W_ * C_);
    const int rl = tid >> 3, c8 = (tid & 7) * 8;   // 32 rows/pass, 4 passes/tile

    #define PW_STAGE_LOAD(ch, sbuf) do { \
        const int kk_ = (ch) * 64; \
        uint32_t base_ = sbase + (uint32_t)(sbuf) * (PW_STG * 2); \
        _Pragma("unroll") \
        for (int rr = 0; rr < 4; rr++) { \
            int r = rl + rr * 32; \
            uint32_t doff = (uint32_t)(r * MP2 + c8) * 2; \
            cp16(base_ + 0*PWT*2 + doff, whi + (o0 + r) * C_ + kk_ + c8); \
            cp16(base_ + 1*PWT*2 + doff, wlo + (o0 + r) * C_ + kk_ + c8); \
            cp16(base_ + 2*PWT*2 + doff, tbh + r * C_ + kk_ + c8); \
            cp16(base_ + 3*PWT*2 + doff, tbl + r * C_ + kk_ + c8); \
        } } while (0)

    PW_STAGE_LOAD(0, 0); CP_COMMIT;

    for (int ch = 0; ch < 4; ch++) {
        if (ch < 3) { PW_STAGE_LOAD(ch + 1, (ch + 1) & 1); CP_COMMIT; CP_WAIT1; }
        else        { CP_WAIT0; }
        __syncthreads();
        const uint32_t sb0 = sbase + (uint32_t)(ch & 1) * (PW_STG * 2);

        #pragma unroll
        for (int ks = 0; ks < 4; ks++) {
            const int k0 = ks * 16;
            uint32_t ah[4][4], al[4][4], bh2[2][4], bl2[2][4];
            #pragma unroll
            for (int mi = 0; mi < 4; mi++) {
                ldmx4(ah[mi], sb0 + (a_off[mi] + k0) * 2);
                ldmx4(al[mi], sb0 + (PWT + a_off[mi] + k0) * 2);
            }
            #pragma unroll
            for (int p = 0; p < 2; p++) {
                ldmx4(bh2[p], sb0 + (2*PWT + b_off[p] + k0) * 2);
                ldmx4(bl2[p], sb0 + (3*PWT + b_off[p] + k0) * 2);
            }
            #pragma unroll
            for (int mi = 0; mi < 4; mi++)
                #pragma unroll
                for (int ni = 0; ni < 4; ni++)
                    mma16816(d[mi][ni], ah[mi], &bh2[ni >> 1][(ni & 1) * 2]);
            #pragma unroll
            for (int mi = 0; mi < 4; mi++)
                #pragma unroll
                for (int ni = 0; ni < 4; ni++)
                    mma16816(d[mi][ni], ah[mi], &bl2[ni >> 1][(ni & 1) * 2]);
            #pragma unroll
            for (int mi = 0; mi < 4; mi++)
                #pragma unroll
                for (int ni = 0; ni < 4; ni++)
                    mma16816(d[mi][ni], al[mi], &bh2[ni >> 1][(ni & 1) * 2]);
        }
        __syncthreads();   // protect buffer reuse by stage ch+2
    }
    #undef PW_STAGE_LOAD

    if (!TRANS) {
        #pragma unroll
        for (int mi = 0; mi < 4; mi++) {
            int o1 = o0 + m0 + mi*16 + (lane >> 2);
            float bv1 = __ldg(&bias[o1]);
            float bv2 = __ldg(&bias[o1 + 8]);
            size_t r1 = ((size_t)bh * C_ + o1) * W_;
            size_t r2 = r1 + 8 * W_;
            #pragma unroll
            for (int ni = 0; ni < 4; ni++) {
                int wc = n0 + ni*8 + (lane & 3)*2;
                __nv_bfloat162 hp, lp;
                split_bf16(d[mi][ni][0] + bv1, hp.x, lp.x);
                split_bf16(d[mi][ni][1] + bv1, hp.y, lp.y);
                *(__nv_bfloat162*)(ohi + r1 + wc) = hp;
                *(__nv_bfloat162*)(olo + r1 + wc) = lp;
                split_bf16(d[mi][ni][2] + bv2, hp.x, lp.x);
                split_bf16(d[mi][ni][3] + bv2, hp.y, lp.y);
                *(__nv_bfloat162*)(ohi + r2 + wc) = hp;
                *(__nv_bfloat162*)(olo + r2 + wc) = lp;
            }
        }
    } else {
        __syncthreads();
        float* DS = (float*)psm;
        #pragma unroll
        for (int mi = 0; mi < 4; mi++) {
            int m_ = m0 + mi*16 + (lane >> 2);
            #pragma unroll
            for (int ni = 0; ni < 4; ni++) {
                int n_ = n0 + ni*8 + (lane & 3)*2;
                DS[n_*132 + m_]         = d[mi][ni][0];
                DS[(n_+1)*132 + m_]     = d[mi][ni][1];
                DS[n_*132 + m_ + 8]     = d[mi][ni][2];
                DS[(n_+1)*132 + m_ + 8] = d[mi][ni][3];
            }
        }
        __syncthreads();
        for (int i = tid; i < 128*32; i += 256) {
            int w = i >> 5, o4 = (i & 31) * 4;
            float4 v = *(float4*)&DS[w*132 + o4];
            float4 bv = *(const float4*)&bias[o0 + o4];
            size_t idx = ((size_t)bh * W_ + w) * C_ + o0 + o4;
            __nv_bfloat162 h01, h23, l01, l23;
            split_bf16(v.x + bv.x, h01.x, l01.x);
            split_bf16(v.y + bv.y, h01.y, l01.y);
            split_bf16(v.z + bv.z, h23.x, l23.x);
            split_bf16(v.w + bv.w, h23.y, l23.y);
            *(__nv_bfloat162*)(ohi + idx)     = h01;
            *(__nv_bfloat162*)(ohi + idx + 2) = h23;
            *(__nv_bfloat162*)(olo + idx)     = l01;
            *(__nv_bfloat162*)(olo + idx + 2) = l23;
        }
    }
}

// ---------------------------------------------------------------------------
// Attention via split-bf16 mma.sync (unchanged from R9).
// ---------------------------------------------------------------------------
#define AMP 136
#define AQHI 0
#define AQLO (128*AMP)
#define AKVHI (2*128*AMP)
#define AKVLO (3*128*AMP)
#define APHI (4*128*AMP)
#define APLO (5*128*AMP)
#define ATT_SMEM (6*128*AMP*2)

__global__ __launch_bounds__(256, 1) void attn_mma_kernel(
    const __nv_bfloat16* __restrict__ qhi, const __nv_bfloat16* __restrict__ qlo,
    const __nv_bfloat16* __restrict__ khi, const __nv_bfloat16* __restrict__ klo,
    const __nv_bfloat16* __restrict__ vhi, const __nv_bfloat16* __restrict__ vlo,
    float* __restrict__ out)
{
    extern __shared__ char smraw[];
    const uint32_t sb = saddr(smraw);
    const int r0 = blockIdx.x * 128;
    const int h = blockIdx.y, b = blockIdx.z;
    const int bh = b * H_ + h;
    const size_t bho = (size_t)bh * (C_ * W_);
    const int tid = threadIdx.x;
    const int wid = tid >> 5, lane = tid & 31;
    const int m0 = wid * 16;
    const float scale = 0.17677669529663687f;

    const int a_off = (m0 + (lane & 15)) * AMP + (lane >> 4) * 8;
    int b_off[8];
    {
        int tl = lane >> 3;
        #pragma unroll
        for (int p = 0; p < 8; p++)
            b_off[p] = (p*16 + (tl >> 1)*8 + (lane & 7)) * AMP + (tl & 1) * 8;
    }
    const int ra = m0 + (lane >> 2);
    const int rb = ra + 8;
    const int pcol0 = (lane & 3) * 2;

    const int rl = tid >> 4, c8 = (tid & 15) * 8;
    #define ALOAD(dstbase, src, rlen, roff, coff) do { \
        _Pragma("unroll") \
        for (int j = 0; j < 8; j++) { \
            int r = rl + j * 16; \
            cp16(sb + ((dstbase) + r * AMP + c8) * 2, \
                 (src) + ((size_t)((roff) + r)) * (rlen) + (coff) + c8); \
        } } while (0)

    float o[16][4];
    #pragma unroll
    for (int nt = 0; nt < 16; nt++) { o[nt][0]=0.f; o[nt][1]=0.f; o[nt][2]=0.f; o[nt][3]=0.f; }
    float m_a = -1e30f, m_b = -1e30f, l_a = 0.f, l_b = 0.f;

    ALOAD(AQHI,  qhi + bho, W_, r0, 0);
    ALOAD(AQLO,  qlo + bho, W_, r0, 0);
    ALOAD(AKVHI, khi + bho, W_, 0, 0);
    ALOAD(AKVLO, klo + bho, W_, 0, 0);
    CP_COMMIT; CP_WAIT0; __syncthreads();

    for (int dt = 0; dt < 2; dt++) {
        float s[16][4];
        #pragma unroll
        for (int nt = 0; nt < 16; nt++) { s[nt][0]=0.f; s[nt][1]=0.f; s[nt][2]=0.f; s[nt][3]=0.f; }
        #pragma unroll
        for (int kw = 0; kw < 8; kw++) {
            uint32_t qh[4], ql[4];
            ldmx4(qh, sb + (AQHI + a_off + kw*16) * 2);
            ldmx4(ql, sb + (AQLO + a_off + kw*16) * 2);
            #pragma unroll
            for (int hf = 0; hf < 2; hf++) {
                uint32_t bh4[4][4], bl4[4][4];
                #pragma unroll
                for (int p = 0; p < 4; p++) {
                    ldmx4(bh4[p], sb + (AKVHI + b_off[hf*4+p] + kw*16) * 2);
                    ldmx4(bl4[p], sb + (AKVLO + b_off[hf*4+p] + kw*16) * 2);
                }
                #pragma unroll
                for (int p8 = 0; p8 < 8; p8++)
                    mma16816(s[hf*8+p8], qh, &bh4[p8 >> 1][(p8 & 1)*2]);
                #pragma unroll
                for (int p8 = 0; p8 < 8; p8++)
                    mma16816(s[hf*8+p8], qh, &bl4[p8 >> 1][(p8 & 1)*2]);
                #pragma unroll
                for (int p8 = 0; p8 < 8; p8++)
                    mma16816(s[hf*8+p8], ql, &bh4[p8 >> 1][(p8 & 1)*2]);
            }
        }
        __syncthreads();
        ALOAD(AKVHI, vhi + bho, C_, 0, dt*128);
        ALOAD(AKVLO, vlo + bho, C_, 0, dt*128);
        CP_COMMIT;

        #pragma unroll
        for (int nt = 0; nt < 16; nt++) {
            s[nt][0] *= scale; s[nt][1] *= scale; s[nt][2] *= scale; s[nt][3] *= scale;
        }
        float mc_a = -1e30f, mc_b = -1e30f;
        #pragma unroll
        for (int nt = 0; nt < 16; nt++) {
            mc_a = fmaxf(mc_a, fmaxf(s[nt][0], s[nt][1]));
            mc_b = fmaxf(mc_b, fmaxf(s[nt][2], s[nt][3]));
        }
        mc_a = fmaxf(mc_a, __shfl_xor_sync(0xffffffffu, mc_a, 1));
        mc_a = fmaxf(mc_a, __shfl_xor_sync(0xffffffffu, mc_a, 2));
        mc_b = fmaxf(mc_b, __shfl_xor_sync(0xffffffffu, mc_b, 1));
        mc_b = fmaxf(mc_b, __shfl_xor_sync(0xffffffffu, mc_b, 2));
        float m_na = fmaxf(m_a, mc_a), m_nb = fmaxf(m_b, mc_b);
        float ca = __expf(m_a - m_na), cb = __expf(m_b - m_nb);
        float la_c = 0.f, lb_c = 0.f;
        #pragma unroll
        for (int nt = 0; nt < 16; nt++) {
            float e0 = __expf(s[nt][0] - m_na), e1 = __expf(s[nt][1] - m_na);
            float e2 = __expf(s[nt][2] - m_nb), e3 = __expf(s[nt][3] - m_nb);
            la_c += e0 + e1; lb_c += e2 + e3;
            int col = nt*8 + pcol0;
            __nv_bfloat162 hp, lp;
            split_bf16(e0, hp.x, lp.x); split_bf16(e1, hp.y, lp.y);
            *(__nv_bfloat162*)(smraw + (APHI + ra*AMP + col)*2) = hp;
            *(__nv_bfloat162*)(smraw + (APLO + ra*AMP + col)*2) = lp;
            split_bf16(e2, hp.x, lp.x); split_bf16(e3, hp.y, lp.y);
            *(__nv_bfloat162*)(smraw + (APHI + rb*AMP + col)*2) = hp;
            *(__nv_bfloat162*)(smraw + (APLO + rb*AMP + col)*2) = lp;
            o[nt][0] *= ca; o[nt][1] *= ca; o[nt][2] *= cb; o[nt][3] *= cb;
        }
        la_c += __shfl_xor_sync(0xffffffffu, la_c, 1);
        la_c += __shfl_xor_sync(0xffffffffu, la_c, 2);
        lb_c += __shfl_xor_sync(0xffffffffu, lb_c, 1);
        lb_c += __shfl_xor_sync(0xffffffffu, lb_c, 2);
        l_a = l_a * ca + la_c;  l_b = l_b * cb + lb_c;
        m_a = m_na;  m_b = m_nb;
        __syncwarp();
        CP_WAIT0; __syncthreads();

        #pragma unroll
        for (int kw = 0; kw < 8; kw++) {
            uint32_t ph[4], pl[4];
            ldmx4(ph, sb + (APHI + a_off + kw*16) * 2);
            ldmx4(pl, sb + (APLO + a_off + kw*16) * 2);
            #pragma unroll
            for (int hf = 0; hf < 2; hf++) {
                uint32_t bh4[4][4], bl4[4][4];
                #pragma unroll
                for (int p = 0; p < 4; p++) {
                    ldmx4(bh4[p], sb + (AKVHI + b_off[hf*4+p] + kw*16) * 2);
                    ldmx4(bl4[p], sb + (AKVLO + b_off[hf*4+p] + kw*16) * 2);
                }
                #pragma unroll
                for (int p8 = 0; p8 < 8; p8++)
                    mma16816(o[hf*8+p8], ph, &bh4[p8 >> 1][(p8 & 1)*2]);
                #pragma unroll
                for (int p8 = 0; p8 < 8; p8++)
                    mma16816(o[hf*8+p8], ph, &bl4[p8 >> 1][(p8 & 1)*2]);
                #pragma unroll
                for (int p8 = 0; p8 < 8; p8++)
                    mma16816(o[hf*8+p8], pl, &bh4[p8 >> 1][(p8 & 1)*2]);
            }
        }

        if (dt == 0) {
            __syncthreads();
            ALOAD(AKVHI, khi + bho, W_, 128, 0);
            ALOAD(AKVLO, klo + bho, W_, 128, 0);
            CP_COMMIT; CP_WAIT0; __syncthreads();
        }
    }
    #undef ALOAD

    float inva = 1.f / l_a, invb = 1.f / l_b;
    __syncthreads();
    float* OS = (float*)(smraw + (size_t)APHI * 2);
    #pragma unroll
    for (int nt = 0; nt < 16; nt++) {
        int col = nt*8 + pcol0;
        *(float2*)&OS[ra*132 + col] = make_float2(o[nt][0]*inva, o[nt][1]*inva);
        *(float2*)&OS[rb*132 + col] = make_float2(o[nt][2]*invb, o[nt][3]*invb);
    }
    __syncthreads();
    for (int i = tid; i < 128*32; i += 256) {
        int r = i >> 5, w4 = (i & 31) * 4;
        *(float4*)(out + ((size_t)(b*C_ + r0 + r)*H_ + h)*W_ + w4) = *(float4*)&OS[r*132 + w4];
    }
}

// ---------------------------------------------------------------------------
extern "C" void kernel_launch(void* const* d_in, const int* in_sizes, int n_in,
                              void* d_out, int out_size)
{
    (void)in_sizes; (void)n_in; (void)out_size;
    const float* hidden = (const float*)d_in[0];
    const float* ctx    = (const float*)d_in[1];
    const float* qdw = (const float*)d_in[2];
    const float* qdb = (const float*)d_in[3];
    const float* qpw = (const float*)d_in[4];
    const float* qpb = (const float*)d_in[5];
    const float* kdw = (const float*)d_in[6];
    const float* kdb = (const float*)d_in[7];
    const float* kpw = (const float*)d_in[8];
    const float* kpb = (const float*)d_in[9];
    const float* vdw = (const float*)d_in[10];
    const float* vdb = (const float*)d_in[11];
    const float* vpw = (const float*)d_in[12];
    const float* vpb = (const float*)d_in[13];
    float* out = (float*)d_out;

    __nv_bfloat16 *whi, *wlo, *thi, *tlo;
    __nv_bfloat16 *qhi, *qlo, *khi, *klo, *vhi, *vlo;
    cudaGetSymbolAddress((void**)&whi, g_whi);
    cudaGetSymbolAddress((void**)&wlo, g_wlo);
    cudaGetSymbolAddress((void**)&thi, g_thi);
    cudaGetSymbolAddress((void**)&tlo, g_tlo);
    cudaGetSymbolAddress((void**)&qhi, g_qhi);
    cudaGetSymbolAddress((void**)&qlo, g_qlo);
    cudaGetSymbolAddress((void**)&khi, g_khi);
    cudaGetSymbolAddress((void**)&klo, g_klo);
    cudaGetSymbolAddress((void**)&vhi, g_vhi);
    cudaGetSymbolAddress((void**)&vlo, g_vlo);

    cudaFuncSetAttribute(pw_mma_kernel<0>, cudaFuncAttributeMaxDynamicSharedMemorySize, PWS_SMEM);
    cudaFuncSetAttribute(pw_mma_kernel<1>, cudaFuncAttributeMaxDynamicSharedMemorySize, PWS_SMEM);
    cudaFuncSetAttribute(attn_mma_kernel, cudaFuncAttributeMaxDynamicSharedMemorySize, ATT_SMEM);

    dim3 dsg(C_/32, H_, B_);
    dim3 pwg(2, H_, B_);
    dim3 atg(2, H_, B_);

    wsplit_kernel<<<C_*C_/256, 256>>>(qpw, whi,            wlo);
    wsplit_kernel<<<C_*C_/256, 256>>>(kpw, whi + C_*C_,    wlo + C_*C_);
    wsplit_kernel<<<C_*C_/256, 256>>>(vpw, whi + 2*C_*C_,  wlo + 2*C_*C_);

    // q -> [b][h][c][w] hi/lo
    dwsplit_kernel<<<dsg, 256>>>(hidden, qdw, qdb, thi, tlo);
    pw_mma_kernel<0><<<pwg, 256, PWS_SMEM>>>(thi, tlo, whi, wlo, qpb, qhi, qlo);
    // k -> [b][h][c][w] hi/lo
    dwsplit_kernel<<<dsg, 256>>>(ctx, kdw, kdb, thi, tlo);
    pw_mma_kernel<0><<<pwg, 256, PWS_SMEM>>>(thi, tlo, whi + C_*C_, wlo + C_*C_, kpb, khi, klo);
    // v -> [b][h][w][c] hi/lo
    dwsplit_kernel<<<dsg, 256>>>(ctx, vdw, vdb, thi, tlo);
    pw_mma_kernel<1><<<pwg, 256, PWS_SMEM>>>(thi, tlo, whi + 2*C_*C_, wlo + 2*C_*C_, vpb, vhi, vlo);

    attn_mma_kernel<<<atg, 256, ATT_SMEM>>>(qhi, qlo, khi, klo, vhi, vlo, out);
}

// round 11
// speedup vs baseline: 3.8261x; 1.0705x over previous
#include <cuda_runtime.h>
#include <cuda_bf16.h>
#include <cstdint>

#define B_ 8
#define C_ 256
#define H_ 128
#define W_ 128
#define NEL (B_*C_*H_*W_)

// Scratch (no allocation allowed -> __device__ globals)
__device__ __nv_bfloat16 g_whi[3 * C_ * C_];   // weight hi, K-major [o][c]
__device__ __nv_bfloat16 g_wlo[3 * C_ * C_];   // weight lo
__device__ __nv_bfloat16 g_t0h[NEL];           // dw-out hi/lo per chain, [b][h][w][c]
__device__ __nv_bfloat16 g_t0l[NEL];
__device__ __nv_bfloat16 g_t1h[NEL];
__device__ __nv_bfloat16 g_t1l[NEL];
__device__ __nv_bfloat16 g_t2h[NEL];
__device__ __nv_bfloat16 g_t2l[NEL];
__device__ __nv_bfloat16 g_qhi[NEL];           // q hi, [b][h][c][w]
__device__ __nv_bfloat16 g_qlo[NEL];
__device__ __nv_bfloat16 g_khi[NEL];           // k hi, [b][h][c][w]
__device__ __nv_bfloat16 g_klo[NEL];
__device__ __nv_bfloat16 g_vhi[NEL];           // v hi, [b][h][w][c]
__device__ __nv_bfloat16 g_vlo[NEL];

// ---- cp.async helpers ----
__device__ __forceinline__ uint32_t saddr(const void* p) {
    return (uint32_t)__cvta_generic_to_shared(p);
}
__device__ __forceinline__ void cp16(uint32_t dst, const void* src) {
    asm volatile("cp.async.cg.shared.global [%0], [%1], 16;" :: "r"(dst), "l"(src));
}
#define CP_COMMIT asm volatile("cp.async.commit_group;")
#define CP_WAIT0  asm volatile("cp.async.wait_group 0;")
#define CP_WAIT1  asm volatile("cp.async.wait_group 1;")

// ---- mma.sync / ldmatrix helpers (plain sm_103 features) ----
__device__ __forceinline__ void ldmx4(uint32_t* r, uint32_t addr) {
    asm volatile("ldmatrix.sync.aligned.m8n8.x4.shared.b16 {%0,%1,%2,%3}, [%4];"
                 : "=r"(r[0]), "=r"(r[1]), "=r"(r[2]), "=r"(r[3]) : "r"(addr));
}
__device__ __forceinline__ void mma16816(float* d, const uint32_t* a, const uint32_t* b) {
    asm volatile(
        "mma.sync.aligned.m16n8k16.row.col.f32.bf16.bf16.f32 "
        "{%0,%1,%2,%3}, {%4,%5,%6,%7}, {%8,%9}, {%0,%1,%2,%3};"
        : "+f"(d[0]), "+f"(d[1]), "+f"(d[2]), "+f"(d[3])
        : "r"(a[0]), "r"(a[1]), "r"(a[2]), "r"(a[3]), "r"(b[0]), "r"(b[1]));
}
__device__ __forceinline__ void split_bf16(float x, __nv_bfloat16& h, __nv_bfloat16& l) {
    h = __float2bfloat16_rn(x);
    l = __float2bfloat16_rn(x - __bfloat162float(h));
}

// ---------------------------------------------------------------------------
// Merged weight split: {q,k,v} pw weights fp32 -> hi/lo bf16. One launch.
// ---------------------------------------------------------------------------
__global__ void wsplit_kernel(const float* __restrict__ qpw,
                              const float* __restrict__ kpw,
                              const float* __restrict__ vpw,
                              __nv_bfloat16* __restrict__ hi,
                              __nv_bfloat16* __restrict__ lo)
{
    int i = blockIdx.x * 256 + threadIdx.x;        // 0 .. 3*C*C
    int chain = i / (C_ * C_), j = i % (C_ * C_);
    const float* W = (chain == 0) ? qpw : (chain == 1) ? kpw : vpw;
    split_bf16(W[j], hi[i], lo[i]);
}

// ---------------------------------------------------------------------------
// MERGED fused depthwise 3x3 + bias + transpose + bf16 split, all 3 chains.
// grid (C/32, H, 3*B), chain = z%3 (k/v adjacent -> ctx L2 reuse), block 256.
// Halo values via register shuffles (no scalar LDG).
// ---------------------------------------------------------------------------
#define DSP 132
__global__ __launch_bounds__(256) void dwsplit_kernel(
    const float* __restrict__ hidden, const float* __restrict__ ctx,
    const float* __restrict__ qdw, const float* __restrict__ qdb,
    const float* __restrict__ kdw, const float* __restrict__ kdb,
    const float* __restrict__ vdw, const float* __restrict__ vdb,
    __nv_bfloat16* __restrict__ t0h, __nv_bfloat16* __restrict__ t0l,
    __nv_bfloat16* __restrict__ t1h, __nv_bfloat16* __restrict__ t1l,
    __nv_bfloat16* __restrict__ t2h, __nv_bfloat16* __restrict__ t2l)
{
    __shared__ float S[32 * DSP];
    const int c0 = blockIdx.x * 32;
    const int h = blockIdx.y;
    const int zz = blockIdx.z;
    const int chain = zz % 3, b = zz / 3;
    const float* x    = (chain == 0) ? hidden : ctx;
    const float* wgt  = (chain == 0) ? qdw : (chain == 1) ? kdw : vdw;
    const float* bias = (chain == 0) ? qdb : (chain == 1) ? kdb : vdb;
    __nv_bfloat16* hi = (chain == 0) ? t0h : (chain == 1) ? t1h : t2h;
    __nv_bfloat16* lo = (chain == 0) ? t0l : (chain == 1) ? t1l : t2l;

    const int tid = threadIdx.x;
    const int tx = tid & 31, ty = tid >> 5;
    const int w0 = tx * 4;

    #pragma unroll
    for (int j = 0; j < 4; j++) {
        const int cc = ty + j * 8;
        const int c = c0 + cc;
        const float* wc = wgt + c * 9;
        const float* plane = x + (b * C_ + c) * (H_ * W_);
        float bv = __ldg(&bias[c]);
        float4 acc = make_float4(bv, bv, bv, bv);
        #pragma unroll
        for (int i = 0; i < 3; i++) {
            int hh = h + i - 1;
            if (hh < 0 || hh >= H_) continue;
            float4 xc = __ldg((const float4*)(plane + hh * W_ + w0));
            float xl = __shfl_up_sync(0xffffffffu, xc.w, 1);
            float xr = __shfl_down_sync(0xffffffffu, xc.x, 1);
            if (tx == 0)  xl = 0.f;
            if (tx == 31) xr = 0.f;
            float wl = __ldg(&wc[i*3+0]), wm = __ldg(&wc[i*3+1]), wr = __ldg(&wc[i*3+2]);
            acc.x += wl*xl   + wm*xc.x + wr*xc.y;
            acc.y += wl*xc.x + wm*xc.y + wr*xc.z;
            acc.z += wl*xc.y + wm*xc.z + wr*xc.w;
            acc.w += wl*xc.z + wm*xc.w + wr*xr;
        }
        *(float4*)&S[cc * DSP + w0] = acc;
    }
    __syncthreads();

    // Phase 2: thread -> (w = tid&127, 16 consecutive c); 32B hi + 32B lo stores
    const int w = tid & 127;
    const int cb = (tid >> 7) * 16;
    __nv_bfloat16 hb[16], lb[16];
    #pragma unroll
    for (int e = 0; e < 16; e++)
        split_bf16(S[(cb + e) * DSP + w], hb[e], lb[e]);
    size_t idx = ((size_t)(b * H_ + h) * W_ + w) * C_ + c0 + cb;
    *(uint4*)(hi + idx)     = *(uint4*)&hb[0];
    *(uint4*)(hi + idx + 8) = *(uint4*)&hb[8];
    *(uint4*)(lo + idx)     = *(uint4*)&lb[0];
    *(uint4*)(lo + idx + 8) = *(uint4*)&lb[8];
}

// ---------------------------------------------------------------------------
// MERGED pointwise 1x1 split-bf16 mma.sync GEMM, all 3 chains in one launch.
// grid (6, H, B): chain = x>>1, o-tile = x&1.  Double-buffered 64-wide K.
// chain 0,1 (q,k): out [b][h][o][w]; chain 2 (v): out [b][h][w][o].
// ---------------------------------------------------------------------------
#define MP2 72
#define PWT (128*MP2)
#define PW_STG (4*PWT)
#define PWS_SMEM (2*PW_STG*2)

__global__ __launch_bounds__(256, 1) void pw_mma_kernel(
    const __nv_bfloat16* __restrict__ t0h, const __nv_bfloat16* __restrict__ t0l,
    const __nv_bfloat16* __restrict__ t1h, const __nv_bfloat16* __restrict__ t1l,
    const __nv_bfloat16* __restrict__ t2h, const __nv_bfloat16* __restrict__ t2l,
    const __nv_bfloat16* __restrict__ whi_b, const __nv_bfloat16* __restrict__ wlo_b,
    const float* __restrict__ qpb, const float* __restrict__ kpb, const float* __restrict__ vpb,
    __nv_bfloat16* __restrict__ q_hi, __nv_bfloat16* __restrict__ q_lo,
    __nv_bfloat16* __restrict__ k_hi, __nv_bfloat16* __restrict__ k_lo,
    __nv_bfloat16* __restrict__ v_hi, __nv_bfloat16* __restrict__ v_lo)
{
    extern __shared__ char psm[];
    const uint32_t sbase = saddr(psm);
    const int chain = blockIdx.x >> 1;
    const int o0 = (blockIdx.x & 1) * 128;
    const int h = blockIdx.y, b = blockIdx.z;
    const int bh = b * H_ + h;
    const int tid = threadIdx.x;
    const int wid = tid >> 5, lane = tid & 31;
    const int m0 = (wid >> 2) * 64;
    const int n0 = (wid & 3) * 32;

    const __nv_bfloat16* thi = (chain == 0) ? t0h : (chain == 1) ? t1h : t2h;
    const __nv_bfloat16* tlo = (chain == 0) ? t0l : (chain == 1) ? t1l : t2l;
    const __nv_bfloat16* whi = whi_b + (size_t)chain * (C_ * C_);
    const __nv_bfloat16* wlo = wlo_b + (size_t)chain * (C_ * C_);
    const float* bias = (chain == 0) ? qpb : (chain == 1) ? kpb : vpb;
    __nv_bfloat16* ohi = (chain == 0) ? q_hi : (chain == 1) ? k_hi : v_hi;
    __nv_bfloat16* olo = (chain == 0) ? q_lo : (chain == 1) ? k_lo : v_lo;

    float d[4][4][4];
    #pragma unroll
    for (int mi = 0; mi < 4; mi++)
        #pragma unroll
        for (int ni = 0; ni < 4; ni++)
            { d[mi][ni][0]=0.f; d[mi][ni][1]=0.f; d[mi][ni][2]=0.f; d[mi][ni][3]=0.f; }

    int a_off[4], b_off[2];
    #pragma unroll
    for (int mi = 0; mi < 4; mi++)
        a_off[mi] = (m0 + mi*16 + (lane & 15)) * MP2 + (lane >> 4) * 8;
    #pragma unroll
    for (int p = 0; p < 2; p++) {
        int tl = lane >> 3;
        b_off[p] = (n0 + p*16 + (tl >> 1)*8 + (lane & 7)) * MP2 + (tl & 1) * 8;
    }

    const __nv_bfloat16* tbh = thi + (size_t)bh * (W_ * C_);
    const __nv_bfloat16* tbl = tlo + (size_t)bh * (W_ * C_);
    const int rl = tid >> 3, c8 = (tid & 7) * 8;

    #define PW_STAGE_LOAD(ch, sbuf) do { \
        const int kk_ = (ch) * 64; \
        uint32_t base_ = sbase + (uint32_t)(sbuf) * (PW_STG * 2); \
        _Pragma("unroll") \
        for (int rr = 0; rr < 4; rr++) { \
            int r = rl + rr * 32; \
            uint32_t doff = (uint32_t)(r * MP2 + c8) * 2; \
            cp16(base_ + 0*PWT*2 + doff, whi + (o0 + r) * C_ + kk_ + c8); \
            cp16(base_ + 1*PWT*2 + doff, wlo + (o0 + r) * C_ + kk_ + c8); \
            cp16(base_ + 2*PWT*2 + doff, tbh + r * C_ + kk_ + c8); \
            cp16(base_ + 3*PWT*2 + doff, tbl + r * C_ + kk_ + c8); \
        } } while (0)

    PW_STAGE_LOAD(0, 0); CP_COMMIT;

    for (int ch = 0; ch < 4; ch++) {
        if (ch < 3) { PW_STAGE_LOAD(ch + 1, (ch + 1) & 1); CP_COMMIT; CP_WAIT1; }
        else        { CP_WAIT0; }
        __syncthreads();
        const uint32_t sb0 = sbase + (uint32_t)(ch & 1) * (PW_STG * 2);

        #pragma unroll
        for (int ks = 0; ks < 4; ks++) {
            const int k0 = ks * 16;
            uint32_t ah[4][4], al[4][4], bh2[2][4], bl2[2][4];
            #pragma unroll
            for (int mi = 0; mi < 4; mi++) {
                ldmx4(ah[mi], sb0 + (a_off[mi] + k0) * 2);
                ldmx4(al[mi], sb0 + (PWT + a_off[mi] + k0) * 2);
            }
            #pragma unroll
            for (int p = 0; p < 2; p++) {
                ldmx4(bh2[p], sb0 + (2*PWT + b_off[p] + k0) * 2);
                ldmx4(bl2[p], sb0 + (3*PWT + b_off[p] + k0) * 2);
            }
            #pragma unroll
            for (int mi = 0; mi < 4; mi++)
                #pragma unroll
                for (int ni = 0; ni < 4; ni++)
                    mma16816(d[mi][ni], ah[mi], &bh2[ni >> 1][(ni & 1) * 2]);
            #pragma unroll
            for (int mi = 0; mi < 4; mi++)
                #pragma unroll
                for (int ni = 0; ni < 4; ni++)
                    mma16816(d[mi][ni], ah[mi], &bl2[ni >> 1][(ni & 1) * 2]);
            #pragma unroll
            for (int mi = 0; mi < 4; mi++)
                #pragma unroll
                for (int ni = 0; ni < 4; ni++)
                    mma16816(d[mi][ni], al[mi], &bh2[ni >> 1][(ni & 1) * 2]);
        }
        __syncthreads();
    }
    #undef PW_STAGE_LOAD

    if (chain != 2) {
        #pragma unroll
        for (int mi = 0; mi < 4; mi++) {
            int o1 = o0 + m0 + mi*16 + (lane >> 2);
            float bv1 = __ldg(&bias[o1]);
            float bv2 = __ldg(&bias[o1 + 8]);
            size_t r1 = ((size_t)bh * C_ + o1) * W_;
            size_t r2 = r1 + 8 * W_;
            #pragma unroll
            for (int ni = 0; ni < 4; ni++) {
                int wc = n0 + ni*8 + (lane & 3)*2;
                __nv_bfloat162 hp, lp;
                split_bf16(d[mi][ni][0] + bv1, hp.x, lp.x);
                split_bf16(d[mi][ni][1] + bv1, hp.y, lp.y);
                *(__nv_bfloat162*)(ohi + r1 + wc) = hp;
                *(__nv_bfloat162*)(olo + r1 + wc) = lp;
                split_bf16(d[mi][ni][2] + bv2, hp.x, lp.x);
                split_bf16(d[mi][ni][3] + bv2, hp.y, lp.y);
                *(__nv_bfloat162*)(ohi + r2 + wc) = hp;
                *(__nv_bfloat162*)(olo + r2 + wc) = lp;
            }
        }
    } else {
        __syncthreads();
        float* DS = (float*)psm;
        #pragma unroll
        for (int mi = 0; mi < 4; mi++) {
            int m_ = m0 + mi*16 + (lane >> 2);
            #pragma unroll
            for (int ni = 0; ni < 4; ni++) {
                int n_ = n0 + ni*8 + (lane & 3)*2;
                DS[n_*132 + m_]         = d[mi][ni][0];
                DS[(n_+1)*132 + m_]     = d[mi][ni][1];
                DS[n_*132 + m_ + 8]     = d[mi][ni][2];
                DS[(n_+1)*132 + m_ + 8] = d[mi][ni][3];
            }
        }
        __syncthreads();
        for (int i = tid; i < 128*32; i += 256) {
            int w = i >> 5, o4 = (i & 31) * 4;
            float4 v = *(float4*)&DS[w*132 + o4];
            float4 bv = *(const float4*)&bias[o0 + o4];
            size_t idx = ((size_t)bh * W_ + w) * C_ + o0 + o4;
            __nv_bfloat162 h01, h23, l01, l23;
            split_bf16(v.x + bv.x, h01.x, l01.x);
            split_bf16(v.y + bv.y, h01.y, l01.y);
            split_bf16(v.z + bv.z, h23.x, l23.x);
            split_bf16(v.w + bv.w, h23.y, l23.y);
            *(__nv_bfloat162*)(ohi + idx)     = h01;
            *(__nv_bfloat162*)(ohi + idx + 2) = h23;
            *(__nv_bfloat162*)(olo + idx)     = l01;
            *(__nv_bfloat162*)(olo + idx + 2) = l23;
        }
    }
}

// ---------------------------------------------------------------------------
// Attention via split-bf16 mma.sync (unchanged from R10).
// ---------------------------------------------------------------------------
#define AMP 136
#define AQHI 0
#define AQLO (128*AMP)
#define AKVHI (2*128*AMP)
#define AKVLO (3*128*AMP)
#define APHI (4*128*AMP)
#define APLO (5*128*AMP)
#define ATT_SMEM (6*128*AMP*2)

__global__ __launch_bounds__(256, 1) void attn_mma_kernel(
    const __nv_bfloat16* __restrict__ qhi, const __nv_bfloat16* __restrict__ qlo,
    const __nv_bfloat16* __restrict__ khi, const __nv_bfloat16* __restrict__ klo,
    const __nv_bfloat16* __restrict__ vhi, const __nv_bfloat16* __restrict__ vlo,
    float* __restrict__ out)
{
    extern __shared__ char smraw[];
    const uint32_t sb = saddr(smraw);
    const int r0 = blockIdx.x * 128;
    const int h = blockIdx.y, b = blockIdx.z;
    const int bh = b * H_ + h;
    const size_t bho = (size_t)bh * (C_ * W_);
    const int tid = threadIdx.x;
    const int wid = tid >> 5, lane = tid & 31;
    const int m0 = wid * 16;
    const float scale = 0.17677669529663687f;

    const int a_off = (m0 + (lane & 15)) * AMP + (lane >> 4) * 8;
    int b_off[8];
    {
        int tl = lane >> 3;
        #pragma unroll
        for (int p = 0; p < 8; p++)
            b_off[p] = (p*16 + (tl >> 1)*8 + (lane & 7)) * AMP + (tl & 1) * 8;
    }
    const int ra = m0 + (lane >> 2);
    const int rb = ra + 8;
    const int pcol0 = (lane & 3) * 2;

    const int rl = tid >> 4, c8 = (tid & 15) * 8;
    #define ALOAD(dstbase, src, rlen, roff, coff) do { \
        _Pragma("unroll") \
        for (int j = 0; j < 8; j++) { \
            int r = rl + j * 16; \
            cp16(sb + ((dstbase) + r * AMP + c8) * 2, \
                 (src) + ((size_t)((roff) + r)) * (rlen) + (coff) + c8); \
        } } while (0)

    float o[16][4];
    #pragma unroll
    for (int nt = 0; nt < 16; nt++) { o[nt][0]=0.f; o[nt][1]=0.f; o[nt][2]=0.f; o[nt][3]=0.f; }
    float m_a = -1e30f, m_b = -1e30f, l_a = 0.f, l_b = 0.f;

    ALOAD(AQHI,  qhi + bho, W_, r0, 0);
    ALOAD(AQLO,  qlo + bho, W_, r0, 0);
    ALOAD(AKVHI, khi + bho, W_, 0, 0);
    ALOAD(AKVLO, klo + bho, W_, 0, 0);
    CP_COMMIT; CP_WAIT0; __syncthreads();

    for (int dt = 0; dt < 2; dt++) {
        float s[16][4];
        #pragma unroll
        for (int nt = 0; nt < 16; nt++) { s[nt][0]=0.f; s[nt][1]=0.f; s[nt][2]=0.f; s[nt][3]=0.f; }
        #pragma unroll
        for (int kw = 0; kw < 8; kw++) {
            uint32_t qh[4], ql[4];
            ldmx4(qh, sb + (AQHI + a_off + kw*16) * 2);
            ldmx4(ql, sb + (AQLO + a_off + kw*16) * 2);
            #pragma unroll
            for (int hf = 0; hf < 2; hf++) {
                uint32_t bh4[4][4], bl4[4][4];
                #pragma unroll
                for (int p = 0; p < 4; p++) {
                    ldmx4(bh4[p], sb + (AKVHI + b_off[hf*4+p] + kw*16) * 2);
                    ldmx4(bl4[p], sb + (AKVLO + b_off[hf*4+p] + kw*16) * 2);
                }
                #pragma unroll
                for (int p8 = 0; p8 < 8; p8++)
                    mma16816(s[hf*8+p8], qh, &bh4[p8 >> 1][(p8 & 1)*2]);
                #pragma unroll
                for (int p8 = 0; p8 < 8; p8++)
                    mma16816(s[hf*8+p8], qh, &bl4[p8 >> 1][(p8 & 1)*2]);
                #pragma unroll
                for (int p8 = 0; p8 < 8; p8++)
                    mma16816(s[hf*8+p8], ql, &bh4[p8 >> 1][(p8 & 1)*2]);
            }
        }
        __syncthreads();
        ALOAD(AKVHI, vhi + bho, C_, 0, dt*128);
        ALOAD(AKVLO, vlo + bho, C_, 0, dt*128);
        CP_COMMIT;

        #pragma unroll
        for (int nt = 0; nt < 16; nt++) {
            s[nt][0] *= scale; s[nt][1] *= scale; s[nt][2] *= scale; s[nt][3] *= scale;
        }
        float mc_a = -1e30f, mc_b = -1e30f;
        #pragma unroll
        for (int nt = 0; nt < 16; nt++) {
            mc_a = fmaxf(mc_a, fmaxf(s[nt][0], s[nt][1]));
            mc_b = fmaxf(mc_b, fmaxf(s[nt][2], s[nt][3]));
        }
        mc_a = fmaxf(mc_a, __shfl_xor_sync(0xffffffffu, mc_a, 1));
        mc_a = fmaxf(mc_a, __shfl_xor_sync(0xffffffffu, mc_a, 2));
        mc_b = fmaxf(mc_b, __shfl_xor_sync(0xffffffffu, mc_b, 1));
        mc_b = fmaxf(mc_b, __shfl_xor_sync(0xffffffffu, mc_b, 2));
        float m_na = fmaxf(m_a, mc_a), m_nb = fmaxf(m_b, mc_b);
        float ca = __expf(m_a - m_na), cb = __expf(m_b - m_nb);
        float la_c = 0.f, lb_c = 0.f;
        #pragma unroll
        for (int nt = 0; nt < 16; nt++) {
            float e0 = __expf(s[nt][0] - m_na), e1 = __expf(s[nt][1] - m_na);
            float e2 = __expf(s[nt][2] - m_nb), e3 = __expf(s[nt][3] - m_nb);
            la_c += e0 + e1; lb_c += e2 + e3;
            int col = nt*8 + pcol0;
            __nv_bfloat162 hp, lp;
            split_bf16(e0, hp.x, lp.x); split_bf16(e1, hp.y, lp.y);
            *(__nv_bfloat162*)(smraw + (APHI + ra*AMP + col)*2) = hp;
            *(__nv_bfloat162*)(smraw + (APLO + ra*AMP + col)*2) = lp;
            split_bf16(e2, hp.x, lp.x); split_bf16(e3, hp.y, lp.y);
            *(__nv_bfloat162*)(smraw + (APHI + rb*AMP + col)*2) = hp;
            *(__nv_bfloat162*)(smraw + (APLO + rb*AMP + col)*2) = lp;
            o[nt][0] *= ca; o[nt][1] *= ca; o[nt][2] *= cb; o[nt][3] *= cb;
        }
        la_c += __shfl_xor_sync(0xffffffffu, la_c, 1);
        la_c += __shfl_xor_sync(0xffffffffu, la_c, 2);
        lb_c += __shfl_xor_sync(0xffffffffu, lb_c, 1);
        lb_c += __shfl_xor_sync(0xffffffffu, lb_c, 2);
        l_a = l_a * ca + la_c;  l_b = l_b * cb + lb_c;
        m_a = m_na;  m_b = m_nb;
        __syncwarp();
        CP_WAIT0; __syncthreads();

        #pragma unroll
        for (int kw = 0; kw < 8; kw++) {
            uint32_t ph[4], pl[4];
            ldmx4(ph, sb + (APHI + a_off + kw*16) * 2);
            ldmx4(pl, sb + (APLO + a_off + kw*16) * 2);
            #pragma unroll
            for (int hf = 0; hf < 2; hf++) {
                uint32_t bh4[4][4], bl4[4][4];
                #pragma unroll
                for (int p = 0; p < 4; p++) {
                    ldmx4(bh4[p], sb + (AKVHI + b_off[hf*4+p] + kw*16) * 2);
                    ldmx4(bl4[p], sb + (AKVLO + b_off[hf*4+p] + kw*16) * 2);
                }
                #pragma unroll
                for (int p8 = 0; p8 < 8; p8++)
                    mma16816(o[hf*8+p8], ph, &bh4[p8 >> 1][(p8 & 1)*2]);
                #pragma unroll
                for (int p8 = 0; p8 < 8; p8++)
                    mma16816(o[hf*8+p8], ph, &bl4[p8 >> 1][(p8 & 1)*2]);
                #pragma unroll
                for (int p8 = 0; p8 < 8; p8++)
                    mma16816(o[hf*8+p8], pl, &bh4[p8 >> 1][(p8 & 1)*2]);
            }
        }

        if (dt == 0) {
            __syncthreads();
            ALOAD(AKVHI, khi + bho, W_, 128, 0);
            ALOAD(AKVLO, klo + bho, W_, 128, 0);
            CP_COMMIT; CP_WAIT0; __syncthreads();
        }
    }
    #undef ALOAD

    float inva = 1.f / l_a, invb = 1.f / l_b;
    __syncthreads();
    float* OS = (float*)(smraw + (size_t)APHI * 2);
    #pragma unroll
    for (int nt = 0; nt < 16; nt++) {
        int col = nt*8 + pcol0;
        *(float2*)&OS[ra*132 + col] = make_float2(o[nt][0]*inva, o[nt][1]*inva);
        *(float2*)&OS[rb*132 + col] = make_float2(o[nt][2]*invb, o[nt][3]*invb);
    }
    __syncthreads();
    for (int i = tid; i < 128*32; i += 256) {
        int r = i >> 5, w4 = (i & 31) * 4;
        *(float4*)(out + ((size_t)(b*C_ + r0 + r)*H_ + h)*W_ + w4) = *(float4*)&OS[r*132 + w4];
    }
}

// ---------------------------------------------------------------------------
extern "C" void kernel_launch(void* const* d_in, const int* in_sizes, int n_in,
                              void* d_out, int out_size)
{
    (void)in_sizes; (void)n_in; (void)out_size;
    const float* hidden = (const float*)d_in[0];
    const float* ctx    = (const float*)d_in[1];
    const float* qdw = (const float*)d_in[2];
    const float* qdb = (const float*)d_in[3];
    const float* qpw = (const float*)d_in[4];
    const float* qpb = (const float*)d_in[5];
    const float* kdw = (const float*)d_in[6];
    const float* kdb = (const float*)d_in[7];
    const float* kpw = (const float*)d_in[8];
    const float* kpb = (const float*)d_in[9];
    const float* vdw = (const float*)d_in[10];
    const float* vdb = (const float*)d_in[11];
    const float* vpw = (const float*)d_in[12];
    const float* vpb = (const float*)d_in[13];
    float* out = (float*)d_out;

    __nv_bfloat16 *whi, *wlo;
    __nv_bfloat16 *t0h, *t0l, *t1h, *t1l, *t2h, *t2l;
    __nv_bfloat16 *qhi, *qlo, *khi, *klo, *vhi, *vlo;
    cudaGetSymbolAddress((void**)&whi, g_whi);
    cudaGetSymbolAddress((void**)&wlo, g_wlo);
    cudaGetSymbolAddress((void**)&t0h, g_t0h);
    cudaGetSymbolAddress((void**)&t0l, g_t0l);
    cudaGetSymbolAddress((void**)&t1h, g_t1h);
    cudaGetSymbolAddress((void**)&t1l, g_t1l);
    cudaGetSymbolAddress((void**)&t2h, g_t2h);
    cudaGetSymbolAddress((void**)&t2l, g_t2l);
    cudaGetSymbolAddress((void**)&qhi, g_qhi);
    cudaGetSymbolAddress((void**)&qlo, g_qlo);
    cudaGetSymbolAddress((void**)&khi, g_khi);
    cudaGetSymbolAddress((void**)&klo, g_klo);
    cudaGetSymbolAddress((void**)&vhi, g_vhi);
    cudaGetSymbolAddress((void**)&vlo, g_vlo);

    cudaFuncSetAttribute(pw_mma_kernel, cudaFuncAttributeMaxDynamicSharedMemorySize, PWS_SMEM);
    cudaFuncSetAttribute(attn_mma_kernel, cudaFuncAttributeMaxDynamicSharedMemorySize, ATT_SMEM);

    dim3 dsg(C_/32, H_, 3*B_);
    dim3 pwg(6, H_, B_);
    dim3 atg(2, H_, B_);

    wsplit_kernel<<<3*C_*C_/256, 256>>>(qpw, kpw, vpw, whi, wlo);
    dwsplit_kernel<<<dsg, 256>>>(hidden, ctx, qdw, qdb, kdw, kdb, vdw, vdb,
                                 t0h, t0l, t1h, t1l, t2h, t2l);
    pw_mma_kernel<<<pwg, 256, PWS_SMEM>>>(t0h, t0l, t1h, t1l, t2h, t2l,
                                          whi, wlo, qpb, kpb, vpb,
                                          qhi, qlo, khi, klo, vhi, vlo);
    attn_mma_kernel<<<atg, 256, ATT_SMEM>>>(qhi, qlo, khi, klo, vhi, vlo, out);
}